// round 1
// baseline (speedup 1.0000x reference)
#include <cuda_runtime.h>
#include <math.h>

// ---------------------------------------------------------------------------
// IDMRF loss, restructured:
//   per (layer, batch):
//     tn,gn   = channel-normalized (target-mean-centered) features  [C,P]
//     S       = tn^T @ gn                                           [P,P]
//     M[hw]   = max_p S[p,hw]          (fused into GEMM epilogue)
//     s1[hw]  = 2/(1 - M + 2*eps);  s2 = M*s1
//     Z[hw]   = sum_p exp(S*s1 - s2)   (stable column softmax denom)
//     aux[hw] = s2 + log(Z)            (= logsumexp_p(S*s1))
//     r[p]    = max_hw (S*s1 - aux)
//     loss   += -w * log( mean_p exp(r[p]) )
// Weights: layer3 w=1 (style), layer4 w=2 (style + content).
// ---------------------------------------------------------------------------

#define MAXB 4
#define MAXP 4096
#define MAXC 512
#define MAX_PB (MAXB * MAXP)

// Scratch (device globals: allocation-free per harness rules)
__device__ float    g_S[(size_t)MAXB * MAXP * MAXP];   // 256 MiB
__device__ float    g_tn[(size_t)MAXB * 256 * 4096];   // fits 4*512*1024 too
__device__ float    g_gn[(size_t)MAXB * 256 * 4096];
__device__ unsigned g_colmax[MAX_PB];
__device__ float    g_Z[MAX_PB];
__device__ float    g_s1[MAX_PB];
__device__ float    g_aux[MAX_PB];
__device__ float    g_rowmax[MAX_PB];

// monotone float <-> unsigned mapping for atomicMax on floats (any sign)
__device__ __forceinline__ unsigned fenc(float f) {
    unsigned u = __float_as_uint(f);
    return (u & 0x80000000u) ? ~u : (u | 0x80000000u);
}
__device__ __forceinline__ float fdec(unsigned u) {
    return __uint_as_float((u & 0x80000000u) ? (u ^ 0x80000000u) : ~u);
}

// FMA-pipe exp (inputs are <= ~0 by construction; avoids MUFU throughput wall)
__device__ __forceinline__ float fast_exp(float x) {
    float y = fmaxf(x * 1.4426950408889634f, -126.0f);
    float n = rintf(y);
    float f = y - n;
    float p = 1.3333558e-3f;
    p = fmaf(p, f, 9.6181291e-3f);
    p = fmaf(p, f, 5.5504109e-2f);
    p = fmaf(p, f, 2.4022651e-1f);
    p = fmaf(p, f, 6.9314718e-1f);
    p = fmaf(p, f, 1.0f);
    return p * __uint_as_float(((unsigned)((int)n + 127)) << 23);
}

// ---------------------------------------------------------------------------
__global__ void init_kernel(int total, int zero_out, float* out) {
    int i = blockIdx.x * blockDim.x + threadIdx.x;
    if (i < total) { g_colmax[i] = 0u; g_Z[i] = 0.0f; }
    if (i == 0 && zero_out) out[0] = 0.0f;
}

// normalize: mean over channels of TARGET, center both, L2-normalize each column
__global__ void normalize_kernel(const float* __restrict__ gen,
                                 const float* __restrict__ tar,
                                 int C, int P) {
    int hw = blockIdx.x * blockDim.x + threadIdx.x;
    int b = blockIdx.y;
    if (hw >= P) return;
    const float* g = gen + (size_t)b * C * P + hw;
    const float* t = tar + (size_t)b * C * P + hw;
    float st = 0.f, stt = 0.f, sg = 0.f, sgg = 0.f;
    for (int c = 0; c < C; c++) {
        float tv = t[(size_t)c * P];
        float gv = g[(size_t)c * P];
        st += tv; stt += tv * tv; sg += gv; sgg += gv * gv;
    }
    float mean = st / (float)C;
    float vt = stt - (float)C * mean * mean;                      // ||t-mean||^2
    float vg = sgg - 2.f * mean * sg + (float)C * mean * mean;    // ||g-mean||^2
    float nt = rsqrtf(fmaxf(vt, 1e-30f));
    float ng = rsqrtf(fmaxf(vg, 1e-30f));
    float* to = g_tn + (size_t)b * C * P + hw;
    float* go = g_gn + (size_t)b * C * P + hw;
    for (int c = 0; c < C; c++) {
        float tv = t[(size_t)c * P];
        float gv = g[(size_t)c * P];
        to[(size_t)c * P] = (tv - mean) * nt;
        go[(size_t)c * P] = (gv - mean) * ng;
    }
}

// S = tn^T @ gn, 128x128 tile, 8x8 per thread; column-max fused in epilogue
#define BM 128
#define BN 128
#define BKK 16
__global__ void __launch_bounds__(256, 2)
gemm_colmax_kernel(int C, int P) {
    __shared__ float As[BKK][BM];
    __shared__ float Bs[BKK][BN];
    __shared__ unsigned cms[BN];
    int b  = blockIdx.z;
    int m0 = blockIdx.y * BM;
    int n0 = blockIdx.x * BN;
    const float* Ab = g_tn + (size_t)b * C * P;
    const float* Bb = g_gn + (size_t)b * C * P;
    int tid = threadIdx.x;
    int tx = tid & 15, ty = tid >> 4;
    if (tid < BN) cms[tid] = 0u;

    float acc[8][8];
#pragma unroll
    for (int i = 0; i < 8; i++)
#pragma unroll
        for (int j = 0; j < 8; j++) acc[i][j] = 0.f;

    for (int k0 = 0; k0 < C; k0 += BKK) {
#pragma unroll
        for (int i = 0; i < 2; i++) {
            int idx = tid + i * 256;
            int r = idx >> 5, c4 = (idx & 31) << 2;
            *(float4*)&As[r][c4] = *(const float4*)&Ab[(size_t)(k0 + r) * P + m0 + c4];
            *(float4*)&Bs[r][c4] = *(const float4*)&Bb[(size_t)(k0 + r) * P + n0 + c4];
        }
        __syncthreads();
#pragma unroll
        for (int k = 0; k < BKK; k++) {
            float a[8], bb[8];
            *(float4*)&a[0]  = *(float4*)&As[k][ty * 4];
            *(float4*)&a[4]  = *(float4*)&As[k][64 + ty * 4];
            *(float4*)&bb[0] = *(float4*)&Bs[k][tx * 4];
            *(float4*)&bb[4] = *(float4*)&Bs[k][64 + tx * 4];
#pragma unroll
            for (int i = 0; i < 8; i++)
#pragma unroll
                for (int j = 0; j < 8; j++)
                    acc[i][j] = fmaf(a[i], bb[j], acc[i][j]);
        }
        __syncthreads();
    }

    float* Sb = g_S + (size_t)b * P * P;
#pragma unroll
    for (int i = 0; i < 8; i++) {
        int mi = m0 + ((i < 4) ? (ty * 4 + i) : (64 + ty * 4 + i - 4));
        *(float4*)&Sb[(size_t)mi * P + n0 + tx * 4]      = *(float4*)&acc[i][0];
        *(float4*)&Sb[(size_t)mi * P + n0 + 64 + tx * 4] = *(float4*)&acc[i][4];
    }
    // column max: local over this thread's 8 rows, then shared, then global
#pragma unroll
    for (int j = 0; j < 8; j++) {
        int cl = (j < 4) ? (tx * 4 + j) : (64 + tx * 4 + j - 4);
        float mx = acc[0][j];
#pragma unroll
        for (int i = 1; i < 8; i++) mx = fmaxf(mx, acc[i][j]);
        atomicMax(&cms[cl], fenc(mx));
    }
    __syncthreads();
    if (tid < BN) atomicMax(&g_colmax[(size_t)b * P + n0 + tid], cms[tid]);
}

// Z[hw] += sum over a row-split of exp(S*s1 - s2)
__global__ void colsum_kernel(int P) {
    int b = blockIdx.z;
    int lane = threadIdx.x & 31;
    int rlane = threadIdx.x >> 5;  // 0..7
    int col = blockIdx.x * 32 + lane;
    int rps = P / gridDim.y;
    int r0 = blockIdx.y * rps;
    float M  = fdec(g_colmax[(size_t)b * P + col]);
    float s1 = 2.0f / (1.0f - M + 2e-5f);
    float s2 = M * s1;
    const float* Sb = g_S + (size_t)b * P * P;
    float acc = 0.f;
    for (int r = r0 + rlane; r < r0 + rps; r += 8)
        acc += fast_exp(fmaf(Sb[(size_t)r * P + col], s1, -s2));
    __shared__ float red[8][32];
    red[rlane][lane] = acc;
    __syncthreads();
    if (rlane == 0) {
        float s = 0.f;
#pragma unroll
        for (int i = 0; i < 8; i++) s += red[i][lane];
        atomicAdd(&g_Z[(size_t)b * P + col], s);
    }
}

__global__ void aux_kernel(int total) {
    int i = blockIdx.x * blockDim.x + threadIdx.x;
    if (i >= total) return;
    float M  = fdec(g_colmax[i]);
    float s1 = 2.0f / (1.0f - M + 2e-5f);
    g_s1[i]  = s1;
    g_aux[i] = fmaf(M, s1, logf(g_Z[i]));
}

// per-row max over all columns of (S*s1 - aux); one warp per row
__global__ void rowmax_kernel(int P) {
    int b = blockIdx.y;
    int row = blockIdx.x * 8 + (threadIdx.x >> 5);
    int lane = threadIdx.x & 31;
    const float* Sr = g_S + (size_t)b * P * P + (size_t)row * P;
    const float* s1b = g_s1 + (size_t)b * P;
    const float* axb = g_aux + (size_t)b * P;
    float mx = -1e30f;
    for (int c = lane; c < P; c += 32)
        mx = fmaxf(mx, fmaf(Sr[c], s1b[c], -axb[c]));
#pragma unroll
    for (int o = 16; o; o >>= 1) mx = fmaxf(mx, __shfl_xor_sync(0xffffffffu, mx, o));
    if (lane == 0) g_rowmax[(size_t)b * P + row] = mx;
}

__global__ void loss_kernel(int P, float w, float* out) {
    int b = blockIdx.x;
    __shared__ float red[256];
    float s = 0.f;
    for (int p = threadIdx.x; p < P; p += 256)
        s += fast_exp(g_rowmax[(size_t)b * P + p]);
    red[threadIdx.x] = s;
    __syncthreads();
    for (int st = 128; st; st >>= 1) {
        if (threadIdx.x < (unsigned)st) red[threadIdx.x] += red[threadIdx.x + st];
        __syncthreads();
    }
    if (threadIdx.x == 0) atomicAdd(out, -w * logf(red[0] / (float)P));
}

// ---------------------------------------------------------------------------
static void run_layer(const float* gen, const float* tar, int B, int C, int P,
                      float w, float* out, int zero_out) {
    int total = B * P;
    init_kernel<<<(total + 255) / 256, 256>>>(total, zero_out, out);
    {
        dim3 g((P + 255) / 256, B);
        normalize_kernel<<<g, 256>>>(gen, tar, C, P);
    }
    {
        dim3 g(P / BN, P / BM, B);
        gemm_colmax_kernel<<<g, 256>>>(C, P);
    }
    {
        dim3 g(P / 32, 8, B);
        colsum_kernel<<<g, 256>>>(P);
    }
    aux_kernel<<<(total + 255) / 256, 256>>>(total);
    {
        dim3 g(P / 8, B);
        rowmax_kernel<<<g, 256>>>(P);
    }
    loss_kernel<<<B, 256>>>(P, w, out);
}

extern "C" void kernel_launch(void* const* d_in, const int* in_sizes, int n_in,
                              void* d_out, int out_size) {
    const float* g3 = (const float*)d_in[0];  // gen_relu3_2 [4,256,64,64]
    const float* t3 = (const float*)d_in[1];  // tar_relu3_2
    const float* g4 = (const float*)d_in[2];  // gen_relu4_2 [4,512,32,32]
    const float* t4 = (const float*)d_in[3];  // tar_relu4_2
    float* out = (float*)d_out;

    run_layer(g3, t3, 4, 256, 64 * 64, 1.0f, out, 1);  // style w=1
    run_layer(g4, t4, 4, 512, 32 * 32, 2.0f, out, 0);  // style + content w=2
}

// round 2
// speedup vs baseline: 1.1409x; 1.1409x over previous
#include <cuda_runtime.h>
#include <cstdint>
#include <math.h>

// ---------------------------------------------------------------------------
// IDMRF loss:
//   per (layer, batch):
//     tn,gn = channel-normalized (target-mean-centered) features [C,P], tf32-rounded
//     S     = tn^T @ gn   (tensor-core tf32 mma, fp32 accum)      [P,P]
//     M[hw] = max_p S[p,hw]                    (fused in GEMM epilogue)
//     s1    = 2/(1-M+2eps); s2 = M*s1
//     Z[hw] = sum_p exp(S*s1 - s2)
//     aux   = s2 + log Z
//     r[p]  = max_hw (S*s1 - aux)
//     loss += -w * log( mean_p exp(r[p]) )
// ---------------------------------------------------------------------------

#define MAXB 4
#define MAXP 4096
#define MAX_PB (MAXB * MAXP)

__device__ float    g_S[(size_t)MAXB * MAXP * MAXP];   // 256 MiB scratch
__device__ float    g_tn[(size_t)MAXB * 256 * 4096];
__device__ float    g_gn[(size_t)MAXB * 256 * 4096];
__device__ unsigned g_colmax[MAX_PB];
__device__ float    g_Z[MAX_PB];
__device__ float    g_s1[MAX_PB];
__device__ float    g_aux[MAX_PB];
__device__ float    g_rowmax[MAX_PB];

__device__ __forceinline__ unsigned fenc(float f) {
    unsigned u = __float_as_uint(f);
    return (u & 0x80000000u) ? ~u : (u | 0x80000000u);
}
__device__ __forceinline__ float fdec(unsigned u) {
    return __uint_as_float((u & 0x80000000u) ? (u ^ 0x80000000u) : ~u);
}

// FMA-pipe exp (avoids MUFU throughput wall)
__device__ __forceinline__ float fast_exp(float x) {
    float y = fmaxf(x * 1.4426950408889634f, -126.0f);
    float n = rintf(y);
    float f = y - n;
    float p = 1.3333558e-3f;
    p = fmaf(p, f, 9.6181291e-3f);
    p = fmaf(p, f, 5.5504109e-2f);
    p = fmaf(p, f, 2.4022651e-1f);
    p = fmaf(p, f, 6.9314718e-1f);
    p = fmaf(p, f, 1.0f);
    return p * __uint_as_float(((unsigned)((int)n + 127)) << 23);
}

__device__ __forceinline__ float to_tf32(float x) {
    uint32_t u;
    asm("cvt.rna.tf32.f32 %0, %1;" : "=r"(u) : "f"(x));
    return __uint_as_float(u);
}

// ---------------------------------------------------------------------------
__global__ void init_kernel(int total, int zero_out, float* out) {
    int i = blockIdx.x * blockDim.x + threadIdx.x;
    if (i < total) { g_colmax[i] = 0u; g_Z[i] = 0.0f; }
    if (i == 0 && zero_out) out[0] = 0.0f;
}

// center by target channel-mean, L2-normalize columns, round to tf32. float4 over hw.
__global__ void normalize_kernel(const float* __restrict__ gen,
                                 const float* __restrict__ tar,
                                 int C, int P) {
    int hw = (blockIdx.x * blockDim.x + threadIdx.x) * 4;
    int b = blockIdx.y;
    if (hw >= P) return;
    const float* g = gen + (size_t)b * C * P + hw;
    const float* t = tar + (size_t)b * C * P + hw;
    float st[4] = {0,0,0,0}, stt[4] = {0,0,0,0}, sg[4] = {0,0,0,0}, sgg[4] = {0,0,0,0};
    for (int c = 0; c < C; c++) {
        float4 tv = *(const float4*)&t[(size_t)c * P];
        float4 gv = *(const float4*)&g[(size_t)c * P];
        st[0] += tv.x; stt[0] += tv.x * tv.x; sg[0] += gv.x; sgg[0] += gv.x * gv.x;
        st[1] += tv.y; stt[1] += tv.y * tv.y; sg[1] += gv.y; sgg[1] += gv.y * gv.y;
        st[2] += tv.z; stt[2] += tv.z * tv.z; sg[2] += gv.z; sgg[2] += gv.z * gv.z;
        st[3] += tv.w; stt[3] += tv.w * tv.w; sg[3] += gv.w; sgg[3] += gv.w * gv.w;
    }
    float mean[4], nt[4], ng[4];
#pragma unroll
    for (int j = 0; j < 4; j++) {
        mean[j] = st[j] / (float)C;
        float vt = stt[j] - (float)C * mean[j] * mean[j];
        float vg = sgg[j] - 2.f * mean[j] * sg[j] + (float)C * mean[j] * mean[j];
        nt[j] = rsqrtf(fmaxf(vt, 1e-30f));
        ng[j] = rsqrtf(fmaxf(vg, 1e-30f));
    }
    float* to = g_tn + (size_t)b * C * P + hw;
    float* go = g_gn + (size_t)b * C * P + hw;
    for (int c = 0; c < C; c++) {
        float4 tv = *(const float4*)&t[(size_t)c * P];
        float4 gv = *(const float4*)&g[(size_t)c * P];
        float4 ot, og;
        ot.x = to_tf32((tv.x - mean[0]) * nt[0]); og.x = to_tf32((gv.x - mean[0]) * ng[0]);
        ot.y = to_tf32((tv.y - mean[1]) * nt[1]); og.y = to_tf32((gv.y - mean[1]) * ng[1]);
        ot.z = to_tf32((tv.z - mean[2]) * nt[2]); og.z = to_tf32((gv.z - mean[2]) * ng[2]);
        ot.w = to_tf32((tv.w - mean[3]) * nt[3]); og.w = to_tf32((gv.w - mean[3]) * ng[3]);
        *(float4*)&to[(size_t)c * P] = ot;
        *(float4*)&go[(size_t)c * P] = og;
    }
}

// ---------------------------------------------------------------------------
// Tensor-core GEMM: S = tn^T @ gn, tf32 mma m16n8k8, 128x128 block, BK=32,
// cp.async double buffered, smem-staged coalesced epilogue + fused colmax.
// ---------------------------------------------------------------------------
#define LDT 136   // smem row stride (floats): conflict-free fragment loads
#define LD2 132   // epilogue staging stride

__global__ void __launch_bounds__(256)
gemm_tf32_colmax(int C, int P) {
    extern __shared__ float smem[];
    __shared__ unsigned cms[128];
    int b  = blockIdx.z;
    int m0 = blockIdx.y * 128;
    int n0 = blockIdx.x * 128;
    const float* Ab = g_tn + (size_t)b * C * P;
    const float* Bb = g_gn + (size_t)b * C * P;
    int tid = threadIdx.x, lane = tid & 31, wid = tid >> 5;
    int wm = (wid & 3) * 32;   // 4 warps in M
    int wn = (wid >> 2) * 64;  // 2 warps in N
    if (tid < 128) cms[tid] = 0u;

    unsigned sA = (unsigned)__cvta_generic_to_shared(smem);
    unsigned sB = sA + 2u * 32u * LDT * 4u;

    float acc[2][8][4];
#pragma unroll
    for (int mt = 0; mt < 2; mt++)
#pragma unroll
        for (int nt = 0; nt < 8; nt++)
#pragma unroll
            for (int j = 0; j < 4; j++) acc[mt][nt][j] = 0.f;

    int nk = C / 32;

    auto issue_stage = [&](int s, int k0) {
#pragma unroll
        for (int i = 0; i < 4; i++) {
            int idx = tid + i * 256;
            int r = idx >> 5;
            int c4 = (idx & 31) * 4;
            unsigned da = sA + (unsigned)(((s * 32 + r) * LDT + c4) * 4);
            const float* pa = Ab + (size_t)(k0 + r) * P + m0 + c4;
            asm volatile("cp.async.cg.shared.global [%0], [%1], 16;" :: "r"(da), "l"(pa));
            unsigned db = sB + (unsigned)(((s * 32 + r) * LDT + c4) * 4);
            const float* pb = Bb + (size_t)(k0 + r) * P + n0 + c4;
            asm volatile("cp.async.cg.shared.global [%0], [%1], 16;" :: "r"(db), "l"(pb));
        }
    };

    issue_stage(0, 0);
    asm volatile("cp.async.commit_group;");

    int ar = lane >> 2, ac = lane & 3;
    for (int kt = 0; kt < nk; kt++) {
        if (kt + 1 < nk) issue_stage((kt + 1) & 1, (kt + 1) * 32);
        asm volatile("cp.async.commit_group;");
        asm volatile("cp.async.wait_group 1;");
        __syncthreads();
        const float* as = smem + (kt & 1) * 32 * LDT;
        const float* bs = smem + 2 * 32 * LDT + (kt & 1) * 32 * LDT;
#pragma unroll
        for (int k8 = 0; k8 < 4; k8++) {
            int kb = k8 * 8;
            uint32_t af[2][4];
#pragma unroll
            for (int mt = 0; mt < 2; mt++) {
                int m = wm + mt * 16 + ar;
                af[mt][0] = __float_as_uint(as[(kb + ac) * LDT + m]);
                af[mt][1] = __float_as_uint(as[(kb + ac) * LDT + m + 8]);
                af[mt][2] = __float_as_uint(as[(kb + ac + 4) * LDT + m]);
                af[mt][3] = __float_as_uint(as[(kb + ac + 4) * LDT + m + 8]);
            }
            uint32_t bf[8][2];
#pragma unroll
            for (int nt = 0; nt < 8; nt++) {
                int n = wn + nt * 8 + ar;
                bf[nt][0] = __float_as_uint(bs[(kb + ac) * LDT + n]);
                bf[nt][1] = __float_as_uint(bs[(kb + ac + 4) * LDT + n]);
            }
#pragma unroll
            for (int mt = 0; mt < 2; mt++)
#pragma unroll
                for (int nt = 0; nt < 8; nt++) {
                    float* c = acc[mt][nt];
                    asm volatile(
                        "mma.sync.aligned.m16n8k8.row.col.f32.tf32.tf32.f32 "
                        "{%0,%1,%2,%3},{%4,%5,%6,%7},{%8,%9},{%0,%1,%2,%3};"
                        : "+f"(c[0]), "+f"(c[1]), "+f"(c[2]), "+f"(c[3])
                        : "r"(af[mt][0]), "r"(af[mt][1]), "r"(af[mt][2]), "r"(af[mt][3]),
                          "r"(bf[nt][0]), "r"(bf[nt][1]));
                }
        }
        __syncthreads();
    }

    // epilogue: stage accumulators to smem (reuse GEMM buffers), then
    // coalesced float4 global store + fused column max.
#pragma unroll
    for (int mt = 0; mt < 2; mt++)
#pragma unroll
        for (int nt = 0; nt < 8; nt++) {
            int r = wm + mt * 16 + ar;
            int c = wn + nt * 8 + ac * 2;
            smem[r * LD2 + c]           = acc[mt][nt][0];
            smem[r * LD2 + c + 1]       = acc[mt][nt][1];
            smem[(r + 8) * LD2 + c]     = acc[mt][nt][2];
            smem[(r + 8) * LD2 + c + 1] = acc[mt][nt][3];
        }
    __syncthreads();

    float* Sb = g_S + (size_t)b * P * P;
    int c4 = (tid & 31) * 4;
    int rb = tid >> 5;
    float mx0 = -1e30f, mx1 = -1e30f, mx2 = -1e30f, mx3 = -1e30f;
#pragma unroll
    for (int i = 0; i < 16; i++) {
        int row = rb + i * 8;
        float4 v = *(float4*)&smem[row * LD2 + c4];
        *(float4*)&Sb[(size_t)(m0 + row) * P + n0 + c4] = v;
        mx0 = fmaxf(mx0, v.x); mx1 = fmaxf(mx1, v.y);
        mx2 = fmaxf(mx2, v.z); mx3 = fmaxf(mx3, v.w);
    }
    atomicMax(&cms[c4],     fenc(mx0));
    atomicMax(&cms[c4 + 1], fenc(mx1));
    atomicMax(&cms[c4 + 2], fenc(mx2));
    atomicMax(&cms[c4 + 3], fenc(mx3));
    __syncthreads();
    if (tid < 128) atomicMax(&g_colmax[(size_t)b * P + n0 + tid], cms[tid]);
}

// ---------------------------------------------------------------------------
// Z[col] += sum over row split of exp(S*s1 - s2); float4 over columns
__global__ void colsum_kernel(int P) {
    int b = blockIdx.z;
    int col = (blockIdx.x * 256 + threadIdx.x) * 4;
    int rps = P >> 3;   // gridDim.y == 8
    int r0 = blockIdx.y * rps;
    const unsigned* cm = g_colmax + (size_t)b * P + col;
    float s1[4], s2[4];
#pragma unroll
    for (int j = 0; j < 4; j++) {
        float M = fdec(cm[j]);
        s1[j] = 2.0f / (1.0f - M + 2e-5f);
        s2[j] = M * s1[j];
    }
    const float* Sb = g_S + (size_t)b * P * P;
    float a0 = 0.f, a1 = 0.f, a2 = 0.f, a3 = 0.f;
    for (int r = r0; r < r0 + rps; r++) {
        float4 v = *(const float4*)&Sb[(size_t)r * P + col];
        a0 += fast_exp(fmaf(v.x, s1[0], -s2[0]));
        a1 += fast_exp(fmaf(v.y, s1[1], -s2[1]));
        a2 += fast_exp(fmaf(v.z, s1[2], -s2[2]));
        a3 += fast_exp(fmaf(v.w, s1[3], -s2[3]));
    }
    float* Zb = g_Z + (size_t)b * P + col;
    atomicAdd(&Zb[0], a0);
    atomicAdd(&Zb[1], a1);
    atomicAdd(&Zb[2], a2);
    atomicAdd(&Zb[3], a3);
}

__global__ void aux_kernel(int total) {
    int i = blockIdx.x * blockDim.x + threadIdx.x;
    if (i >= total) return;
    float M = fdec(g_colmax[i]);
    float s1 = 2.0f / (1.0f - M + 2e-5f);
    g_s1[i] = s1;
    g_aux[i] = fmaf(M, s1, logf(g_Z[i]));
}

// per-row max of (S*s1 - aux); one warp per row, float4 loads
__global__ void rowmax_kernel(int P) {
    int b = blockIdx.y;
    int row = blockIdx.x * 8 + (threadIdx.x >> 5);
    int lane = threadIdx.x & 31;
    const float* Sr  = g_S + (size_t)b * P * P + (size_t)row * P;
    const float* s1b = g_s1 + (size_t)b * P;
    const float* axb = g_aux + (size_t)b * P;
    float mx = -1e30f;
    for (int c = lane * 4; c < P; c += 128) {
        float4 v = *(const float4*)&Sr[c];
        float4 s = *(const float4*)&s1b[c];
        float4 a = *(const float4*)&axb[c];
        mx = fmaxf(mx, fmaf(v.x, s.x, -a.x));
        mx = fmaxf(mx, fmaf(v.y, s.y, -a.y));
        mx = fmaxf(mx, fmaf(v.z, s.z, -a.z));
        mx = fmaxf(mx, fmaf(v.w, s.w, -a.w));
    }
#pragma unroll
    for (int o = 16; o; o >>= 1) mx = fmaxf(mx, __shfl_xor_sync(0xffffffffu, mx, o));
    if (lane == 0) g_rowmax[(size_t)b * P + row] = mx;
}

__global__ void loss_kernel(int P, float w, float* out) {
    int b = blockIdx.x;
    __shared__ float red[256];
    float s = 0.f;
    for (int p = threadIdx.x; p < P; p += 256)
        s += fast_exp(g_rowmax[(size_t)b * P + p]);
    red[threadIdx.x] = s;
    __syncthreads();
    for (int st = 128; st; st >>= 1) {
        if (threadIdx.x < (unsigned)st) red[threadIdx.x] += red[threadIdx.x + st];
        __syncthreads();
    }
    if (threadIdx.x == 0) atomicAdd(out, -w * logf(red[0] / (float)P));
}

// ---------------------------------------------------------------------------
#define GEMM_SMEM (2 * 2 * 32 * LDT * 4)  // 69632 bytes

static void run_layer(const float* gen, const float* tar, int B, int C, int P,
                      float w, float* out, int zero_out) {
    int total = B * P;
    init_kernel<<<(total + 255) / 256, 256>>>(total, zero_out, out);
    {
        dim3 g((P / 4 + 255) / 256, B);
        normalize_kernel<<<g, 256>>>(gen, tar, C, P);
    }
    {
        dim3 g(P / 128, P / 128, B);
        gemm_tf32_colmax<<<g, 256, GEMM_SMEM>>>(C, P);
    }
    {
        dim3 g(P / 1024, 8, B);
        colsum_kernel<<<g, 256>>>(P);
    }
    aux_kernel<<<(total + 255) / 256, 256>>>(total);
    {
        dim3 g(P / 8, B);
        rowmax_kernel<<<g, 256>>>(P);
    }
    loss_kernel<<<B, 256>>>(P, w, out);
}

extern "C" void kernel_launch(void* const* d_in, const int* in_sizes, int n_in,
                              void* d_out, int out_size) {
    const float* g3 = (const float*)d_in[0];  // gen_relu3_2 [4,256,64,64]
    const float* t3 = (const float*)d_in[1];  // tar_relu3_2
    const float* g4 = (const float*)d_in[2];  // gen_relu4_2 [4,512,32,32]
    const float* t4 = (const float*)d_in[3];  // tar_relu4_2
    float* out = (float*)d_out;

    cudaFuncSetAttribute(gemm_tf32_colmax,
                         cudaFuncAttributeMaxDynamicSharedMemorySize, GEMM_SMEM);

    run_layer(g3, t3, 4, 256, 64 * 64, 1.0f, out, 1);  // style w=1
    run_layer(g4, t4, 4, 512, 32 * 32, 2.0f, out, 0);  // style + content w=2
}

// round 3
// speedup vs baseline: 1.4935x; 1.3091x over previous
#include <cuda_runtime.h>
#include <cstdint>
#include <math.h>

// ---------------------------------------------------------------------------
// IDMRF loss:
//   per (layer, batch):
//     tn,gn = channel-normalized (target-mean-centered) features [C,P], tf32-rounded
//     S     = tn^T @ gn   (tensor-core tf32 mma, fp32 accum)      [P,P]
//     M[hw] = max_p S[p,hw]                    (fused in GEMM epilogue)
//     s1    = 2/(1-M+2eps); s2 = M*s1
//     Z[hw] = sum_p exp(S*s1 - s2)
//     aux   = s2 + log Z
//     r[p]  = max_hw (S*s1 - aux)
//     loss += -w * log( mean_p exp(r[p]) )
// ---------------------------------------------------------------------------

#define MAXB 4
#define MAXP 4096
#define MAX_PB (MAXB * MAXP)

__device__ float    g_S[(size_t)MAXB * MAXP * MAXP];   // 256 MiB scratch
__device__ float    g_tn[(size_t)MAXB * 256 * 4096];
__device__ float    g_gn[(size_t)MAXB * 256 * 4096];
__device__ unsigned g_colmax[MAX_PB];
__device__ float    g_Z[MAX_PB];
__device__ float    g_s1[MAX_PB];
__device__ float    g_aux[MAX_PB];
__device__ float    g_rowmax[MAX_PB];

__device__ __forceinline__ unsigned fenc(float f) {
    unsigned u = __float_as_uint(f);
    return (u & 0x80000000u) ? ~u : (u | 0x80000000u);
}
__device__ __forceinline__ float fdec(unsigned u) {
    return __uint_as_float((u & 0x80000000u) ? (u ^ 0x80000000u) : ~u);
}

// FMA-pipe exp (avoids MUFU throughput wall)
__device__ __forceinline__ float fast_exp(float x) {
    float y = fmaxf(x * 1.4426950408889634f, -126.0f);
    float n = rintf(y);
    float f = y - n;
    float p = 1.3333558e-3f;
    p = fmaf(p, f, 9.6181291e-3f);
    p = fmaf(p, f, 5.5504109e-2f);
    p = fmaf(p, f, 2.4022651e-1f);
    p = fmaf(p, f, 6.9314718e-1f);
    p = fmaf(p, f, 1.0f);
    return p * __uint_as_float(((unsigned)((int)n + 127)) << 23);
}

__device__ __forceinline__ float to_tf32(float x) {
    uint32_t u;
    asm("cvt.rna.tf32.f32 %0, %1;" : "=r"(u) : "f"(x));
    return __uint_as_float(u);
}

// ---------------------------------------------------------------------------
__global__ void init_kernel(int total, int zero_out, float* out) {
    int i = blockIdx.x * blockDim.x + threadIdx.x;
    if (i < total) { g_colmax[i] = 0u; g_Z[i] = 0.0f; }
    if (i == 0 && zero_out) out[0] = 0.0f;
}

// center by target channel-mean, L2-normalize columns, round to tf32. float4 over hw.
__global__ void normalize_kernel(const float* __restrict__ gen,
                                 const float* __restrict__ tar,
                                 int C, int P) {
    int hw = (blockIdx.x * blockDim.x + threadIdx.x) * 4;
    int b = blockIdx.y;
    if (hw >= P) return;
    const float* g = gen + (size_t)b * C * P + hw;
    const float* t = tar + (size_t)b * C * P + hw;
    float st[4] = {0,0,0,0}, stt[4] = {0,0,0,0}, sg[4] = {0,0,0,0}, sgg[4] = {0,0,0,0};
    for (int c = 0; c < C; c++) {
        float4 tv = *(const float4*)&t[(size_t)c * P];
        float4 gv = *(const float4*)&g[(size_t)c * P];
        st[0] += tv.x; stt[0] += tv.x * tv.x; sg[0] += gv.x; sgg[0] += gv.x * gv.x;
        st[1] += tv.y; stt[1] += tv.y * tv.y; sg[1] += gv.y; sgg[1] += gv.y * gv.y;
        st[2] += tv.z; stt[2] += tv.z * tv.z; sg[2] += gv.z; sgg[2] += gv.z * gv.z;
        st[3] += tv.w; stt[3] += tv.w * tv.w; sg[3] += gv.w; sgg[3] += gv.w * gv.w;
    }
    float mean[4], nt[4], ng[4];
#pragma unroll
    for (int j = 0; j < 4; j++) {
        mean[j] = st[j] / (float)C;
        float vt = stt[j] - (float)C * mean[j] * mean[j];
        float vg = sgg[j] - 2.f * mean[j] * sg[j] + (float)C * mean[j] * mean[j];
        nt[j] = rsqrtf(fmaxf(vt, 1e-30f));
        ng[j] = rsqrtf(fmaxf(vg, 1e-30f));
    }
    float* to = g_tn + (size_t)b * C * P + hw;
    float* go = g_gn + (size_t)b * C * P + hw;
    for (int c = 0; c < C; c++) {
        float4 tv = *(const float4*)&t[(size_t)c * P];
        float4 gv = *(const float4*)&g[(size_t)c * P];
        float4 ot, og;
        ot.x = to_tf32((tv.x - mean[0]) * nt[0]); og.x = to_tf32((gv.x - mean[0]) * ng[0]);
        ot.y = to_tf32((tv.y - mean[1]) * nt[1]); og.y = to_tf32((gv.y - mean[1]) * ng[1]);
        ot.z = to_tf32((tv.z - mean[2]) * nt[2]); og.z = to_tf32((gv.z - mean[2]) * ng[2]);
        ot.w = to_tf32((tv.w - mean[3]) * nt[3]); og.w = to_tf32((gv.w - mean[3]) * ng[3]);
        *(float4*)&to[(size_t)c * P] = ot;
        *(float4*)&go[(size_t)c * P] = og;
    }
}

// ---------------------------------------------------------------------------
// Tensor-core GEMM: S = tn^T @ gn, tf32 mma m16n8k8, 128x128 block, BK=32,
// cp.async double buffered, smem-staged coalesced epilogue + fused colmax.
// ---------------------------------------------------------------------------
#define LDT 136   // smem row stride (floats): conflict-free fragment loads
#define LD2 132   // epilogue staging stride

__global__ void __launch_bounds__(256)
gemm_tf32_colmax(int C, int P) {
    extern __shared__ float smem[];
    __shared__ unsigned cms[128];
    int b  = blockIdx.z;
    int m0 = blockIdx.y * 128;
    int n0 = blockIdx.x * 128;
    const float* Ab = g_tn + (size_t)b * C * P;
    const float* Bb = g_gn + (size_t)b * C * P;
    int tid = threadIdx.x, lane = tid & 31, wid = tid >> 5;
    int wm = (wid & 3) * 32;   // 4 warps in M
    int wn = (wid >> 2) * 64;  // 2 warps in N
    if (tid < 128) cms[tid] = 0u;

    unsigned sA = (unsigned)__cvta_generic_to_shared(smem);
    unsigned sB = sA + 2u * 32u * LDT * 4u;

    float acc[2][8][4];
#pragma unroll
    for (int mt = 0; mt < 2; mt++)
#pragma unroll
        for (int nt = 0; nt < 8; nt++)
#pragma unroll
            for (int j = 0; j < 4; j++) acc[mt][nt][j] = 0.f;

    int nk = C / 32;

    auto issue_stage = [&](int s, int k0) {
#pragma unroll
        for (int i = 0; i < 4; i++) {
            int idx = tid + i * 256;
            int r = idx >> 5;
            int c4 = (idx & 31) * 4;
            unsigned da = sA + (unsigned)(((s * 32 + r) * LDT + c4) * 4);
            const float* pa = Ab + (size_t)(k0 + r) * P + m0 + c4;
            asm volatile("cp.async.cg.shared.global [%0], [%1], 16;" :: "r"(da), "l"(pa));
            unsigned db = sB + (unsigned)(((s * 32 + r) * LDT + c4) * 4);
            const float* pb = Bb + (size_t)(k0 + r) * P + n0 + c4;
            asm volatile("cp.async.cg.shared.global [%0], [%1], 16;" :: "r"(db), "l"(pb));
        }
    };

    issue_stage(0, 0);
    asm volatile("cp.async.commit_group;");

    int ar = lane >> 2, ac = lane & 3;
    for (int kt = 0; kt < nk; kt++) {
        if (kt + 1 < nk) issue_stage((kt + 1) & 1, (kt + 1) * 32);
        asm volatile("cp.async.commit_group;");
        asm volatile("cp.async.wait_group 1;");
        __syncthreads();
        const float* as = smem + (kt & 1) * 32 * LDT;
        const float* bs = smem + 2 * 32 * LDT + (kt & 1) * 32 * LDT;
#pragma unroll
        for (int k8 = 0; k8 < 4; k8++) {
            int kb = k8 * 8;
            uint32_t af[2][4];
#pragma unroll
            for (int mt = 0; mt < 2; mt++) {
                int m = wm + mt * 16 + ar;
                af[mt][0] = __float_as_uint(as[(kb + ac) * LDT + m]);
                af[mt][1] = __float_as_uint(as[(kb + ac) * LDT + m + 8]);
                af[mt][2] = __float_as_uint(as[(kb + ac + 4) * LDT + m]);
                af[mt][3] = __float_as_uint(as[(kb + ac + 4) * LDT + m + 8]);
            }
            uint32_t bf[8][2];
#pragma unroll
            for (int nt = 0; nt < 8; nt++) {
                int n = wn + nt * 8 + ar;
                bf[nt][0] = __float_as_uint(bs[(kb + ac) * LDT + n]);
                bf[nt][1] = __float_as_uint(bs[(kb + ac + 4) * LDT + n]);
            }
#pragma unroll
            for (int mt = 0; mt < 2; mt++)
#pragma unroll
                for (int nt = 0; nt < 8; nt++) {
                    float* c = acc[mt][nt];
                    asm volatile(
                        "mma.sync.aligned.m16n8k8.row.col.f32.tf32.tf32.f32 "
                        "{%0,%1,%2,%3},{%4,%5,%6,%7},{%8,%9},{%0,%1,%2,%3};"
                        : "+f"(c[0]), "+f"(c[1]), "+f"(c[2]), "+f"(c[3])
                        : "r"(af[mt][0]), "r"(af[mt][1]), "r"(af[mt][2]), "r"(af[mt][3]),
                          "r"(bf[nt][0]), "r"(bf[nt][1]));
                }
        }
        __syncthreads();
    }

    // epilogue: stage accumulators to smem (reuse GEMM buffers), then
    // coalesced float4 global store + fused column max.
#pragma unroll
    for (int mt = 0; mt < 2; mt++)
#pragma unroll
        for (int nt = 0; nt < 8; nt++) {
            int r = wm + mt * 16 + ar;
            int c = wn + nt * 8 + ac * 2;
            smem[r * LD2 + c]           = acc[mt][nt][0];
            smem[r * LD2 + c + 1]       = acc[mt][nt][1];
            smem[(r + 8) * LD2 + c]     = acc[mt][nt][2];
            smem[(r + 8) * LD2 + c + 1] = acc[mt][nt][3];
        }
    __syncthreads();

    float* Sb = g_S + (size_t)b * P * P;
    int c4 = (tid & 31) * 4;
    int rb = tid >> 5;
    float mx0 = -1e30f, mx1 = -1e30f, mx2 = -1e30f, mx3 = -1e30f;
#pragma unroll
    for (int i = 0; i < 16; i++) {
        int row = rb + i * 8;
        float4 v = *(float4*)&smem[row * LD2 + c4];
        *(float4*)&Sb[(size_t)(m0 + row) * P + n0 + c4] = v;
        mx0 = fmaxf(mx0, v.x); mx1 = fmaxf(mx1, v.y);
        mx2 = fmaxf(mx2, v.z); mx3 = fmaxf(mx3, v.w);
    }
    atomicMax(&cms[c4],     fenc(mx0));
    atomicMax(&cms[c4 + 1], fenc(mx1));
    atomicMax(&cms[c4 + 2], fenc(mx2));
    atomicMax(&cms[c4 + 3], fenc(mx3));
    __syncthreads();
    if (tid < 128) atomicMax(&g_colmax[(size_t)b * P + n0 + tid], cms[tid]);
}

// ---------------------------------------------------------------------------
// Z[col] += sum over row split of exp(S*s1 - s2); float4 over columns.
// gridDim.y = 64 row-splits for occupancy + MLP.
__global__ void colsum_kernel(int P) {
    int b = blockIdx.z;
    int col = (blockIdx.x * 256 + threadIdx.x) * 4;
    int rps = P >> 6;   // gridDim.y == 64
    int r0 = blockIdx.y * rps;
    const unsigned* cm = g_colmax + (size_t)b * P + col;
    float s1[4], s2[4];
#pragma unroll
    for (int j = 0; j < 4; j++) {
        float M = fdec(cm[j]);
        s1[j] = 2.0f / (1.0f - M + 2e-5f);
        s2[j] = M * s1[j];
    }
    const float* Sb = g_S + (size_t)b * P * P;
    float a0 = 0.f, a1 = 0.f, a2 = 0.f, a3 = 0.f;
#pragma unroll 4
    for (int r = r0; r < r0 + rps; r++) {
        float4 v = *(const float4*)&Sb[(size_t)r * P + col];
        a0 += fast_exp(fmaf(v.x, s1[0], -s2[0]));
        a1 += fast_exp(fmaf(v.y, s1[1], -s2[1]));
        a2 += fast_exp(fmaf(v.z, s1[2], -s2[2]));
        a3 += fast_exp(fmaf(v.w, s1[3], -s2[3]));
    }
    float* Zb = g_Z + (size_t)b * P + col;
    atomicAdd(&Zb[0], a0);
    atomicAdd(&Zb[1], a1);
    atomicAdd(&Zb[2], a2);
    atomicAdd(&Zb[3], a3);
}

__global__ void aux_kernel(int total) {
    int i = blockIdx.x * blockDim.x + threadIdx.x;
    if (i >= total) return;
    float M = fdec(g_colmax[i]);
    float s1 = 2.0f / (1.0f - M + 2e-5f);
    g_s1[i] = s1;
    g_aux[i] = fmaf(M, s1, logf(g_Z[i]));
}

// per-row max of (S*s1 - aux); one warp per row, two independent float4 streams
__global__ void rowmax_kernel(int P) {
    int b = blockIdx.y;
    int row = blockIdx.x * 8 + (threadIdx.x >> 5);
    int lane = threadIdx.x & 31;
    const float* Sr  = g_S + (size_t)b * P * P + (size_t)row * P;
    const float* s1b = g_s1 + (size_t)b * P;
    const float* axb = g_aux + (size_t)b * P;
    float mxa = -1e30f, mxb = -1e30f;
    for (int c = lane * 4; c < P; c += 256) {
        float4 v0 = *(const float4*)&Sr[c];
        float4 v1 = *(const float4*)&Sr[c + 128];
        float4 s0 = *(const float4*)&s1b[c];
        float4 s1v = *(const float4*)&s1b[c + 128];
        float4 a0 = *(const float4*)&axb[c];
        float4 a1 = *(const float4*)&axb[c + 128];
        mxa = fmaxf(mxa, fmaf(v0.x, s0.x, -a0.x));
        mxa = fmaxf(mxa, fmaf(v0.y, s0.y, -a0.y));
        mxa = fmaxf(mxa, fmaf(v0.z, s0.z, -a0.z));
        mxa = fmaxf(mxa, fmaf(v0.w, s0.w, -a0.w));
        mxb = fmaxf(mxb, fmaf(v1.x, s1v.x, -a1.x));
        mxb = fmaxf(mxb, fmaf(v1.y, s1v.y, -a1.y));
        mxb = fmaxf(mxb, fmaf(v1.z, s1v.z, -a1.z));
        mxb = fmaxf(mxb, fmaf(v1.w, s1v.w, -a1.w));
    }
    float mx = fmaxf(mxa, mxb);
#pragma unroll
    for (int o = 16; o; o >>= 1) mx = fmaxf(mx, __shfl_xor_sync(0xffffffffu, mx, o));
    if (lane == 0) g_rowmax[(size_t)b * P + row] = mx;
}

__global__ void loss_kernel(int P, float w, float* out) {
    int b = blockIdx.x;
    __shared__ float red[256];
    float s = 0.f;
    for (int p = threadIdx.x; p < P; p += 256)
        s += fast_exp(g_rowmax[(size_t)b * P + p]);
    red[threadIdx.x] = s;
    __syncthreads();
    for (int st = 128; st; st >>= 1) {
        if (threadIdx.x < (unsigned)st) red[threadIdx.x] += red[threadIdx.x + st];
        __syncthreads();
    }
    if (threadIdx.x == 0) atomicAdd(out, -w * logf(red[0] / (float)P));
}

// ---------------------------------------------------------------------------
#define GEMM_SMEM (2 * 2 * 32 * LDT * 4)  // 69632 bytes

static void run_layer(const float* gen, const float* tar, int B, int C, int P,
                      float w, float* out, int zero_out) {
    int total = B * P;
    init_kernel<<<(total + 255) / 256, 256>>>(total, zero_out, out);
    {
        dim3 g((P / 4 + 255) / 256, B);
        normalize_kernel<<<g, 256>>>(gen, tar, C, P);
    }
    {
        dim3 g(P / 128, P / 128, B);
        gemm_tf32_colmax<<<g, 256, GEMM_SMEM>>>(C, P);
    }
    {
        dim3 g(P / 1024, 64, B);
        colsum_kernel<<<g, 256>>>(P);
    }
    aux_kernel<<<(total + 255) / 256, 256>>>(total);
    {
        dim3 g(P / 8, B);
        rowmax_kernel<<<g, 256>>>(P);
    }
    loss_kernel<<<B, 256>>>(P, w, out);
}

extern "C" void kernel_launch(void* const* d_in, const int* in_sizes, int n_in,
                              void* d_out, int out_size) {
    const float* g3 = (const float*)d_in[0];  // gen_relu3_2 [4,256,64,64]
    const float* t3 = (const float*)d_in[1];  // tar_relu3_2
    const float* g4 = (const float*)d_in[2];  // gen_relu4_2 [4,512,32,32]
    const float* t4 = (const float*)d_in[3];  // tar_relu4_2
    float* out = (float*)d_out;

    cudaFuncSetAttribute(gemm_tf32_colmax,
                         cudaFuncAttributeMaxDynamicSharedMemorySize, GEMM_SMEM);

    run_layer(g3, t3, 4, 256, 64 * 64, 1.0f, out, 1);  // style w=1
    run_layer(g4, t4, 4, 512, 32 * 32, 2.0f, out, 0);  // style + content w=2
}

// round 4
// speedup vs baseline: 1.5230x; 1.0197x over previous
#include <cuda_runtime.h>
#include <cuda_fp16.h>
#include <cstdint>
#include <math.h>

// ---------------------------------------------------------------------------
// IDMRF loss:
//   per (layer, batch):
//     tn,gn = channel-normalized (target-mean-centered) features [C,P], fp16
//     S     = tn^T @ gn   (fp16 mma m16n8k16, fp32 accum)         [P,P]
//     M[hw] = max_p S[p,hw]                    (fused in GEMM epilogue)
//     s1    = 2/(1-M+2eps); s2 = M*s1
//     Z[hw] = sum_p exp(S*s1 - s2)
//     aux   = s2 + log Z
//     r[p]  = max_hw (S*s1 - aux)
//     loss += -w * log( mean_p exp(r[p]) )
// ---------------------------------------------------------------------------

#define MAXB 4
#define MAXP 4096
#define MAX_PB (MAXB * MAXP)

__device__ float    g_S[(size_t)MAXB * MAXP * MAXP];   // 256 MiB scratch
__device__ __half   g_tn[(size_t)MAXB * 256 * 4096];
__device__ __half   g_gn[(size_t)MAXB * 256 * 4096];
__device__ unsigned g_colmax[MAX_PB];
__device__ float    g_Z[MAX_PB];
__device__ float    g_s1[MAX_PB];
__device__ float    g_aux[MAX_PB];
__device__ float    g_rowmax[MAX_PB];

__device__ __forceinline__ unsigned fenc(float f) {
    unsigned u = __float_as_uint(f);
    return (u & 0x80000000u) ? ~u : (u | 0x80000000u);
}
__device__ __forceinline__ float fdec(unsigned u) {
    return __uint_as_float((u & 0x80000000u) ? (u ^ 0x80000000u) : ~u);
}

// FMA-pipe exp (avoids MUFU throughput wall)
__device__ __forceinline__ float fast_exp(float x) {
    float y = fmaxf(x * 1.4426950408889634f, -126.0f);
    float n = rintf(y);
    float f = y - n;
    float p = 1.3333558e-3f;
    p = fmaf(p, f, 9.6181291e-3f);
    p = fmaf(p, f, 5.5504109e-2f);
    p = fmaf(p, f, 2.4022651e-1f);
    p = fmaf(p, f, 6.9314718e-1f);
    p = fmaf(p, f, 1.0f);
    return p * __uint_as_float(((unsigned)((int)n + 127)) << 23);
}

__device__ __forceinline__ void ldsm4t(uint32_t& r0, uint32_t& r1,
                                       uint32_t& r2, uint32_t& r3, unsigned addr) {
    asm volatile("ldmatrix.sync.aligned.m8n8.x4.trans.shared.b16 {%0,%1,%2,%3},[%4];"
                 : "=r"(r0), "=r"(r1), "=r"(r2), "=r"(r3) : "r"(addr));
}

// ---------------------------------------------------------------------------
__global__ void init_kernel(int total, int zero_out, float* out) {
    int i = blockIdx.x * blockDim.x + threadIdx.x;
    if (i < total) { g_colmax[i] = 0u; g_Z[i] = 0.0f; }
    if (i == 0 && zero_out) out[0] = 0.0f;
}

// center by target channel-mean, L2-normalize columns, emit fp16. float4 over hw.
__global__ void normalize_kernel(const float* __restrict__ gen,
                                 const float* __restrict__ tar,
                                 int C, int P) {
    int hw = (blockIdx.x * blockDim.x + threadIdx.x) * 4;
    int b = blockIdx.y;
    if (hw >= P) return;
    const float* g = gen + (size_t)b * C * P + hw;
    const float* t = tar + (size_t)b * C * P + hw;
    float st[4] = {0,0,0,0}, stt[4] = {0,0,0,0}, sg[4] = {0,0,0,0}, sgg[4] = {0,0,0,0};
    for (int c = 0; c < C; c++) {
        float4 tv = *(const float4*)&t[(size_t)c * P];
        float4 gv = *(const float4*)&g[(size_t)c * P];
        st[0] += tv.x; stt[0] += tv.x * tv.x; sg[0] += gv.x; sgg[0] += gv.x * gv.x;
        st[1] += tv.y; stt[1] += tv.y * tv.y; sg[1] += gv.y; sgg[1] += gv.y * gv.y;
        st[2] += tv.z; stt[2] += tv.z * tv.z; sg[2] += gv.z; sgg[2] += gv.z * gv.z;
        st[3] += tv.w; stt[3] += tv.w * tv.w; sg[3] += gv.w; sgg[3] += gv.w * gv.w;
    }
    float mean[4], nt[4], ng[4];
#pragma unroll
    for (int j = 0; j < 4; j++) {
        mean[j] = st[j] / (float)C;
        float vt = stt[j] - (float)C * mean[j] * mean[j];
        float vg = sgg[j] - 2.f * mean[j] * sg[j] + (float)C * mean[j] * mean[j];
        nt[j] = rsqrtf(fmaxf(vt, 1e-30f));
        ng[j] = rsqrtf(fmaxf(vg, 1e-30f));
    }
    __half* to = g_tn + (size_t)b * C * P + hw;
    __half* go = g_gn + (size_t)b * C * P + hw;
    for (int c = 0; c < C; c++) {
        float4 tv = *(const float4*)&t[(size_t)c * P];
        float4 gv = *(const float4*)&g[(size_t)c * P];
        __half2 t01 = __floats2half2_rn((tv.x - mean[0]) * nt[0], (tv.y - mean[1]) * nt[1]);
        __half2 t23 = __floats2half2_rn((tv.z - mean[2]) * nt[2], (tv.w - mean[3]) * nt[3]);
        __half2 g01 = __floats2half2_rn((gv.x - mean[0]) * ng[0], (gv.y - mean[1]) * ng[1]);
        __half2 g23 = __floats2half2_rn((gv.z - mean[2]) * ng[2], (gv.w - mean[3]) * ng[3]);
        uint2 tp, gp;
        tp.x = *(unsigned*)&t01; tp.y = *(unsigned*)&t23;
        gp.x = *(unsigned*)&g01; gp.y = *(unsigned*)&g23;
        *(uint2*)&to[(size_t)c * P] = tp;
        *(uint2*)&go[(size_t)c * P] = gp;
    }
}

// ---------------------------------------------------------------------------
// FP16 tensor-core GEMM: S = tn^T @ gn, mma m16n8k16, 128x128 block, BK=32,
// cp.async double buffered, ldmatrix.x4.trans fragments,
// smem-staged coalesced fp32 epilogue + fused colmax.
// ---------------------------------------------------------------------------
#define LDH 136                      // smem row stride in halves (272 B)
#define ASTAGE (32 * LDH * 2)        // 8704 B per tile-stage
#define LD2 132                      // epilogue staging stride (floats)

__global__ void __launch_bounds__(256)
gemm_fp16_colmax(int C, int P) {
    extern __shared__ float smem[];
    __shared__ unsigned cms[128];
    int b  = blockIdx.z;
    int m0 = blockIdx.y * 128;
    int n0 = blockIdx.x * 128;
    const __half* Ab = g_tn + (size_t)b * C * P;
    const __half* Bb = g_gn + (size_t)b * C * P;
    int tid = threadIdx.x, lane = tid & 31, wid = tid >> 5;
    int wm = (wid & 3) * 32;   // 4 warps in M
    int wn = (wid >> 2) * 64;  // 2 warps in N
    if (tid < 128) cms[tid] = 0u;

    unsigned sA = (unsigned)__cvta_generic_to_shared(smem);
    unsigned sB = sA + 2u * ASTAGE;

    float acc[2][8][4];
#pragma unroll
    for (int mt = 0; mt < 2; mt++)
#pragma unroll
        for (int nt = 0; nt < 8; nt++)
#pragma unroll
            for (int j = 0; j < 4; j++) acc[mt][nt][j] = 0.f;

    int nk = C / 32;

    auto issue_stage = [&](int s, int k0) {
#pragma unroll
        for (int i = 0; i < 2; i++) {
            int idx = tid + i * 256;        // 0..511 chunks of 16B
            int r = idx >> 4;               // k-row 0..31
            int cm = (idx & 15) * 8;        // half offset
            unsigned da = sA + (unsigned)s * ASTAGE + (unsigned)((r * LDH + cm) * 2);
            const __half* pa = Ab + (size_t)(k0 + r) * P + m0 + cm;
            asm volatile("cp.async.cg.shared.global [%0], [%1], 16;" :: "r"(da), "l"(pa));
            unsigned db = sB + (unsigned)s * ASTAGE + (unsigned)((r * LDH + cm) * 2);
            const __half* pb = Bb + (size_t)(k0 + r) * P + n0 + cm;
            asm volatile("cp.async.cg.shared.global [%0], [%1], 16;" :: "r"(db), "l"(pb));
        }
    };

    issue_stage(0, 0);
    asm volatile("cp.async.commit_group;");

    int g = lane >> 3, li = lane & 7;
    int akoff = (g >> 1) << 3, amoff = (g & 1) << 3;   // A tile-group offsets
    int bkoff = (g & 1) << 3,  bnoff = (g >> 1) << 3;  // B tile-group offsets

    for (int kt = 0; kt < nk; kt++) {
        if (kt + 1 < nk) issue_stage((kt + 1) & 1, (kt + 1) * 32);
        asm volatile("cp.async.commit_group;");
        asm volatile("cp.async.wait_group 1;");
        __syncthreads();
        unsigned aS = sA + (unsigned)(kt & 1) * ASTAGE;
        unsigned bS = sB + (unsigned)(kt & 1) * ASTAGE;
#pragma unroll
        for (int k16 = 0; k16 < 2; k16++) {
            int kb = k16 * 16;
            uint32_t af[2][4];
#pragma unroll
            for (int mt = 0; mt < 2; mt++) {
                int row = kb + akoff + li;
                int col = wm + mt * 16 + amoff;
                ldsm4t(af[mt][0], af[mt][1], af[mt][2], af[mt][3],
                       aS + (unsigned)((row * LDH + col) * 2));
            }
            uint32_t bf[8][2];
#pragma unroll
            for (int np = 0; np < 4; np++) {
                int row = kb + bkoff + li;
                int col = wn + np * 16 + bnoff;
                uint32_t r0, r1, r2, r3;
                ldsm4t(r0, r1, r2, r3, bS + (unsigned)((row * LDH + col) * 2));
                bf[np * 2][0] = r0; bf[np * 2][1] = r1;
                bf[np * 2 + 1][0] = r2; bf[np * 2 + 1][1] = r3;
            }
#pragma unroll
            for (int mt = 0; mt < 2; mt++)
#pragma unroll
                for (int nt = 0; nt < 8; nt++) {
                    float* c = acc[mt][nt];
                    asm volatile(
                        "mma.sync.aligned.m16n8k16.row.col.f32.f16.f16.f32 "
                        "{%0,%1,%2,%3},{%4,%5,%6,%7},{%8,%9},{%0,%1,%2,%3};"
                        : "+f"(c[0]), "+f"(c[1]), "+f"(c[2]), "+f"(c[3])
                        : "r"(af[mt][0]), "r"(af[mt][1]), "r"(af[mt][2]), "r"(af[mt][3]),
                          "r"(bf[nt][0]), "r"(bf[nt][1]));
                }
        }
        __syncthreads();
    }

    // epilogue: stage accumulators to smem, coalesced float4 store + col max
    int ar = lane >> 2, ac = lane & 3;
#pragma unroll
    for (int mt = 0; mt < 2; mt++)
#pragma unroll
        for (int nt = 0; nt < 8; nt++) {
            int r = wm + mt * 16 + ar;
            int c = wn + nt * 8 + ac * 2;
            smem[r * LD2 + c]           = acc[mt][nt][0];
            smem[r * LD2 + c + 1]       = acc[mt][nt][1];
            smem[(r + 8) * LD2 + c]     = acc[mt][nt][2];
            smem[(r + 8) * LD2 + c + 1] = acc[mt][nt][3];
        }
    __syncthreads();

    float* Sb = g_S + (size_t)b * P * P;
    int c4 = (tid & 31) * 4;
    int rb = tid >> 5;
    float mx0 = -1e30f, mx1 = -1e30f, mx2 = -1e30f, mx3 = -1e30f;
#pragma unroll
    for (int i = 0; i < 16; i++) {
        int row = rb + i * 8;
        float4 v = *(float4*)&smem[row * LD2 + c4];
        *(float4*)&Sb[(size_t)(m0 + row) * P + n0 + c4] = v;
        mx0 = fmaxf(mx0, v.x); mx1 = fmaxf(mx1, v.y);
        mx2 = fmaxf(mx2, v.z); mx3 = fmaxf(mx3, v.w);
    }
    atomicMax(&cms[c4],     fenc(mx0));
    atomicMax(&cms[c4 + 1], fenc(mx1));
    atomicMax(&cms[c4 + 2], fenc(mx2));
    atomicMax(&cms[c4 + 3], fenc(mx3));
    __syncthreads();
    if (tid < 128) atomicMax(&g_colmax[(size_t)b * P + n0 + tid], cms[tid]);
}

// ---------------------------------------------------------------------------
// Z[col] += sum over row split of exp(S*s1 - s2); float4 over columns.
__global__ void colsum_kernel(int P) {
    int b = blockIdx.z;
    int col = (blockIdx.x * 256 + threadIdx.x) * 4;
    int rps = P >> 6;   // gridDim.y == 64
    int r0 = blockIdx.y * rps;
    const unsigned* cm = g_colmax + (size_t)b * P + col;
    float s1[4], s2[4];
#pragma unroll
    for (int j = 0; j < 4; j++) {
        float M = fdec(cm[j]);
        s1[j] = 2.0f / (1.0f - M + 2e-5f);
        s2[j] = M * s1[j];
    }
    const float* Sb = g_S + (size_t)b * P * P;
    float a0 = 0.f, a1 = 0.f, a2 = 0.f, a3 = 0.f;
#pragma unroll 8
    for (int r = r0; r < r0 + rps; r++) {
        float4 v = *(const float4*)&Sb[(size_t)r * P + col];
        a0 += fast_exp(fmaf(v.x, s1[0], -s2[0]));
        a1 += fast_exp(fmaf(v.y, s1[1], -s2[1]));
        a2 += fast_exp(fmaf(v.z, s1[2], -s2[2]));
        a3 += fast_exp(fmaf(v.w, s1[3], -s2[3]));
    }
    float* Zb = g_Z + (size_t)b * P + col;
    atomicAdd(&Zb[0], a0);
    atomicAdd(&Zb[1], a1);
    atomicAdd(&Zb[2], a2);
    atomicAdd(&Zb[3], a3);
}

__global__ void aux_kernel(int total) {
    int i = blockIdx.x * blockDim.x + threadIdx.x;
    if (i >= total) return;
    float M = fdec(g_colmax[i]);
    float s1 = 2.0f / (1.0f - M + 2e-5f);
    g_s1[i] = s1;
    g_aux[i] = fmaf(M, s1, logf(g_Z[i]));
}

// per-row max of (S*s1 - aux); one warp per row, two independent float4 streams
__global__ void rowmax_kernel(int P) {
    int b = blockIdx.y;
    int row = blockIdx.x * 8 + (threadIdx.x >> 5);
    int lane = threadIdx.x & 31;
    const float* Sr  = g_S + (size_t)b * P * P + (size_t)row * P;
    const float* s1b = g_s1 + (size_t)b * P;
    const float* axb = g_aux + (size_t)b * P;
    float mxa = -1e30f, mxb = -1e30f;
    for (int c = lane * 4; c < P; c += 256) {
        float4 v0 = *(const float4*)&Sr[c];
        float4 v1 = *(const float4*)&Sr[c + 128];
        float4 s0 = *(const float4*)&s1b[c];
        float4 s1v = *(const float4*)&s1b[c + 128];
        float4 a0 = *(const float4*)&axb[c];
        float4 a1 = *(const float4*)&axb[c + 128];
        mxa = fmaxf(mxa, fmaf(v0.x, s0.x, -a0.x));
        mxa = fmaxf(mxa, fmaf(v0.y, s0.y, -a0.y));
        mxa = fmaxf(mxa, fmaf(v0.z, s0.z, -a0.z));
        mxa = fmaxf(mxa, fmaf(v0.w, s0.w, -a0.w));
        mxb = fmaxf(mxb, fmaf(v1.x, s1v.x, -a1.x));
        mxb = fmaxf(mxb, fmaf(v1.y, s1v.y, -a1.y));
        mxb = fmaxf(mxb, fmaf(v1.z, s1v.z, -a1.z));
        mxb = fmaxf(mxb, fmaf(v1.w, s1v.w, -a1.w));
    }
    float mx = fmaxf(mxa, mxb);
#pragma unroll
    for (int o = 16; o; o >>= 1) mx = fmaxf(mx, __shfl_xor_sync(0xffffffffu, mx, o));
    if (lane == 0) g_rowmax[(size_t)b * P + row] = mx;
}

__global__ void loss_kernel(int P, float w, float* out) {
    int b = blockIdx.x;
    __shared__ float red[256];
    float s = 0.f;
    for (int p = threadIdx.x; p < P; p += 256)
        s += fast_exp(g_rowmax[(size_t)b * P + p]);
    red[threadIdx.x] = s;
    __syncthreads();
    for (int st = 128; st; st >>= 1) {
        if (threadIdx.x < (unsigned)st) red[threadIdx.x] += red[threadIdx.x + st];
        __syncthreads();
    }
    if (threadIdx.x == 0) atomicAdd(out, -w * logf(red[0] / (float)P));
}

// ---------------------------------------------------------------------------
#define GEMM_SMEM (128 * LD2 * 4)   // 67584 B (epilogue; stages use 34816 B)

static void run_layer(const float* gen, const float* tar, int B, int C, int P,
                      float w, float* out, int zero_out) {
    int total = B * P;
    init_kernel<<<(total + 255) / 256, 256>>>(total, zero_out, out);
    {
        dim3 g((P / 4 + 255) / 256, B);
        normalize_kernel<<<g, 256>>>(gen, tar, C, P);
    }
    {
        dim3 g(P / 128, P / 128, B);
        gemm_fp16_colmax<<<g, 256, GEMM_SMEM>>>(C, P);
    }
    {
        dim3 g(P / 1024, 64, B);
        colsum_kernel<<<g, 256>>>(P);
    }
    aux_kernel<<<(total + 255) / 256, 256>>>(total);
    {
        dim3 g(P / 8, B);
        rowmax_kernel<<<g, 256>>>(P);
    }
    loss_kernel<<<B, 256>>>(P, w, out);
}

extern "C" void kernel_launch(void* const* d_in, const int* in_sizes, int n_in,
                              void* d_out, int out_size) {
    const float* g3 = (const float*)d_in[0];  // gen_relu3_2 [4,256,64,64]
    const float* t3 = (const float*)d_in[1];  // tar_relu3_2
    const float* g4 = (const float*)d_in[2];  // gen_relu4_2 [4,512,32,32]
    const float* t4 = (const float*)d_in[3];  // tar_relu4_2
    float* out = (float*)d_out;

    cudaFuncSetAttribute(gemm_fp16_colmax,
                         cudaFuncAttributeMaxDynamicSharedMemorySize, GEMM_SMEM);

    run_layer(g3, t3, 4, 256, 64 * 64, 1.0f, out, 1);  // style w=1
    run_layer(g4, t4, 4, 512, 32 * 32, 2.0f, out, 0);  // style + content w=2
}

// round 5
// speedup vs baseline: 2.7797x; 1.8252x over previous
#include <cuda_runtime.h>
#include <cuda_fp16.h>
#include <cstdint>
#include <math.h>

// ---------------------------------------------------------------------------
// IDMRF loss (see earlier rounds for derivation).
// ---------------------------------------------------------------------------

#define MAXB 4
#define MAXP 4096
#define MAX_PB (MAXB * MAXP)

__device__ float    g_S[(size_t)MAXB * MAXP * MAXP];   // 256 MiB scratch
__device__ __half   g_tn[(size_t)MAXB * 256 * 4096];
__device__ __half   g_gn[(size_t)MAXB * 256 * 4096];
__device__ unsigned g_colmax[MAX_PB];
__device__ float    g_Z[MAX_PB];
__device__ float    g_s1[MAX_PB];
__device__ float    g_aux[MAX_PB];
__device__ float    g_rowmax[MAX_PB];
// normalize stats
__device__ float    g_st[MAX_PB], g_stt[MAX_PB], g_sg[MAX_PB], g_sgg[MAX_PB];
__device__ float    g_mean[MAX_PB], g_nt[MAX_PB], g_ng[MAX_PB];

__device__ __forceinline__ unsigned fenc(float f) {
    unsigned u = __float_as_uint(f);
    return (u & 0x80000000u) ? ~u : (u | 0x80000000u);
}
__device__ __forceinline__ float fdec(unsigned u) {
    return __uint_as_float((u & 0x80000000u) ? (u ^ 0x80000000u) : ~u);
}

__device__ __forceinline__ float fast_exp(float x) {
    float y = fmaxf(x * 1.4426950408889634f, -126.0f);
    float n = rintf(y);
    float f = y - n;
    float p = 1.3333558e-3f;
    p = fmaf(p, f, 9.6181291e-3f);
    p = fmaf(p, f, 5.5504109e-2f);
    p = fmaf(p, f, 2.4022651e-1f);
    p = fmaf(p, f, 6.9314718e-1f);
    p = fmaf(p, f, 1.0f);
    return p * __uint_as_float(((unsigned)((int)n + 127)) << 23);
}

__device__ __forceinline__ void ldsm4t(uint32_t& r0, uint32_t& r1,
                                       uint32_t& r2, uint32_t& r3, unsigned addr) {
    asm volatile("ldmatrix.sync.aligned.m8n8.x4.trans.shared.b16 {%0,%1,%2,%3},[%4];"
                 : "=r"(r0), "=r"(r1), "=r"(r2), "=r"(r3) : "r"(addr));
}

// ---------------------------------------------------------------------------
__global__ void init_kernel(int total, int zero_out, float* out) {
    int i = blockIdx.x * blockDim.x + threadIdx.x;
    if (i < total) {
        g_colmax[i] = 0u; g_Z[i] = 0.0f;
        g_st[i] = 0.f; g_stt[i] = 0.f; g_sg[i] = 0.f; g_sgg[i] = 0.f;
    }
    if (i == 0 && zero_out) out[0] = 0.0f;
}

// ---- normalize phase 1: split-K partial stats, atomic accumulate ----------
__global__ void stats_kernel(const float* __restrict__ gen,
                             const float* __restrict__ tar,
                             int C, int P, int CPS) {  // CPS = channels per split
    int hw = blockIdx.x * 1024 + threadIdx.x * 4;
    int b = blockIdx.z;
    int c0 = blockIdx.y * CPS;
    const float* g = gen + (size_t)b * C * P + (size_t)c0 * P + hw;
    const float* t = tar + (size_t)b * C * P + (size_t)c0 * P + hw;
    float st[4] = {0,0,0,0}, stt[4] = {0,0,0,0}, sg[4] = {0,0,0,0}, sgg[4] = {0,0,0,0};
#pragma unroll 4
    for (int c = 0; c < CPS; c++) {
        float4 tv = *(const float4*)&t[(size_t)c * P];
        float4 gv = *(const float4*)&g[(size_t)c * P];
        st[0] += tv.x; stt[0] += tv.x * tv.x; sg[0] += gv.x; sgg[0] += gv.x * gv.x;
        st[1] += tv.y; stt[1] += tv.y * tv.y; sg[1] += gv.y; sgg[1] += gv.y * gv.y;
        st[2] += tv.z; stt[2] += tv.z * tv.z; sg[2] += gv.z; sgg[2] += gv.z * gv.z;
        st[3] += tv.w; stt[3] += tv.w * tv.w; sg[3] += gv.w; sgg[3] += gv.w * gv.w;
    }
    size_t base = (size_t)b * P + hw;
#pragma unroll
    for (int j = 0; j < 4; j++) {
        atomicAdd(&g_st[base + j],  st[j]);
        atomicAdd(&g_stt[base + j], stt[j]);
        atomicAdd(&g_sg[base + j],  sg[j]);
        atomicAdd(&g_sgg[base + j], sgg[j]);
    }
}

// ---- normalize phase 2: per-column mean and inverse norms ------------------
__global__ void finalize_kernel(int total, int C) {
    int i = blockIdx.x * blockDim.x + threadIdx.x;
    if (i >= total) return;
    float st = g_st[i], stt = g_stt[i], sg = g_sg[i], sgg = g_sgg[i];
    float mean = st / (float)C;
    float vt = stt - (float)C * mean * mean;
    float vg = sgg - 2.f * mean * sg + (float)C * mean * mean;
    g_mean[i] = mean;
    g_nt[i] = rsqrtf(fmaxf(vt, 1e-30f));
    g_ng[i] = rsqrtf(fmaxf(vg, 1e-30f));
}

// ---- normalize phase 3: write pass, fully parallel over (b,c,hw) ----------
__global__ void write_kernel(const float* __restrict__ gen,
                             const float* __restrict__ tar,
                             int C, int P, int p4shift) {
    int idx = blockIdx.x * 256 + threadIdx.x;     // float4 index within batch
    int b = blockIdx.y;
    int c = idx >> p4shift;
    int hw = (idx & ((1 << p4shift) - 1)) * 4;
    size_t off = (size_t)b * C * P + (size_t)c * P + hw;
    size_t pb = (size_t)b * P + hw;
    float4 tv = *(const float4*)&tar[off];
    float4 gv = *(const float4*)&gen[off];
    float4 mean = *(const float4*)&g_mean[pb];
    float4 nt   = *(const float4*)&g_nt[pb];
    float4 ng   = *(const float4*)&g_ng[pb];
    __half2 t01 = __floats2half2_rn((tv.x - mean.x) * nt.x, (tv.y - mean.y) * nt.y);
    __half2 t23 = __floats2half2_rn((tv.z - mean.z) * nt.z, (tv.w - mean.w) * nt.w);
    __half2 g01 = __floats2half2_rn((gv.x - mean.x) * ng.x, (gv.y - mean.y) * ng.y);
    __half2 g23 = __floats2half2_rn((gv.z - mean.z) * ng.z, (gv.w - mean.w) * ng.w);
    uint2 tp, gp;
    tp.x = *(unsigned*)&t01; tp.y = *(unsigned*)&t23;
    gp.x = *(unsigned*)&g01; gp.y = *(unsigned*)&g23;
    *(uint2*)&g_tn[off] = tp;
    *(uint2*)&g_gn[off] = gp;
}

// ---------------------------------------------------------------------------
// FP16 tensor-core GEMM: S = tn^T @ gn, mma m16n8k16, 128x128 block, BK=32,
// 3-stage cp.async pipeline, ldmatrix.x4.trans, fused colmax epilogue.
// ---------------------------------------------------------------------------
#define LDH 136                      // smem row stride in halves (272 B)
#define ASTAGE (32 * LDH * 2)        // 8704 B per tile per stage
#define NSTAGE 3
#define LD2 132                      // epilogue staging stride (floats)

__global__ void __launch_bounds__(256)
gemm_fp16_colmax(int C, int P) {
    extern __shared__ float smem[];
    __shared__ unsigned cms[128];
    int b  = blockIdx.z;
    int m0 = blockIdx.y * 128;
    int n0 = blockIdx.x * 128;
    const __half* Ab = g_tn + (size_t)b * C * P;
    const __half* Bb = g_gn + (size_t)b * C * P;
    int tid = threadIdx.x, lane = tid & 31, wid = tid >> 5;
    int wm = (wid & 3) * 32;   // 4 warps in M
    int wn = (wid >> 2) * 64;  // 2 warps in N
    if (tid < 128) cms[tid] = 0u;

    unsigned sA = (unsigned)__cvta_generic_to_shared(smem);
    unsigned sB = sA + (unsigned)NSTAGE * ASTAGE;

    float acc[2][8][4];
#pragma unroll
    for (int mt = 0; mt < 2; mt++)
#pragma unroll
        for (int nt = 0; nt < 8; nt++)
#pragma unroll
            for (int j = 0; j < 4; j++) acc[mt][nt][j] = 0.f;

    int nk = C / 32;

    auto issue_stage = [&](int s, int k0) {
#pragma unroll
        for (int i = 0; i < 2; i++) {
            int idx = tid + i * 256;        // 512 chunks of 16B per tile
            int r = idx >> 4;               // k-row 0..31
            int cm = (idx & 15) * 8;        // half offset
            unsigned da = sA + (unsigned)s * ASTAGE + (unsigned)((r * LDH + cm) * 2);
            const __half* pa = Ab + (size_t)(k0 + r) * P + m0 + cm;
            asm volatile("cp.async.cg.shared.global [%0], [%1], 16;" :: "r"(da), "l"(pa));
            unsigned db = sB + (unsigned)s * ASTAGE + (unsigned)((r * LDH + cm) * 2);
            const __half* pb = Bb + (size_t)(k0 + r) * P + n0 + cm;
            asm volatile("cp.async.cg.shared.global [%0], [%1], 16;" :: "r"(db), "l"(pb));
        }
    };

    issue_stage(0, 0);
    asm volatile("cp.async.commit_group;");
    issue_stage(1, 32);
    asm volatile("cp.async.commit_group;");

    int g = lane >> 3, li = lane & 7;
    int akoff = (g >> 1) << 3, amoff = (g & 1) << 3;
    int bkoff = (g & 1) << 3,  bnoff = (g >> 1) << 3;

    int sidx = 0;  // stage index = kt % 3
    for (int kt = 0; kt < nk; kt++) {
        asm volatile("cp.async.wait_group 1;");
        __syncthreads();
        if (kt + 2 < nk) {
            int s2 = sidx + 2; if (s2 >= NSTAGE) s2 -= NSTAGE;
            issue_stage(s2, (kt + 2) * 32);
        }
        asm volatile("cp.async.commit_group;");
        unsigned aS = sA + (unsigned)sidx * ASTAGE;
        unsigned bS = sB + (unsigned)sidx * ASTAGE;
#pragma unroll
        for (int k16 = 0; k16 < 2; k16++) {
            int kb = k16 * 16;
            uint32_t af[2][4];
#pragma unroll
            for (int mt = 0; mt < 2; mt++) {
                int row = kb + akoff + li;
                int col = wm + mt * 16 + amoff;
                ldsm4t(af[mt][0], af[mt][1], af[mt][2], af[mt][3],
                       aS + (unsigned)((row * LDH + col) * 2));
            }
            uint32_t bf[8][2];
#pragma unroll
            for (int np = 0; np < 4; np++) {
                int row = kb + bkoff + li;
                int col = wn + np * 16 + bnoff;
                uint32_t r0, r1, r2, r3;
                ldsm4t(r0, r1, r2, r3, bS + (unsigned)((row * LDH + col) * 2));
                bf[np * 2][0] = r0; bf[np * 2][1] = r1;
                bf[np * 2 + 1][0] = r2; bf[np * 2 + 1][1] = r3;
            }
#pragma unroll
            for (int mt = 0; mt < 2; mt++)
#pragma unroll
                for (int nt = 0; nt < 8; nt++) {
                    float* c = acc[mt][nt];
                    asm volatile(
                        "mma.sync.aligned.m16n8k16.row.col.f32.f16.f16.f32 "
                        "{%0,%1,%2,%3},{%4,%5,%6,%7},{%8,%9},{%0,%1,%2,%3};"
                        : "+f"(c[0]), "+f"(c[1]), "+f"(c[2]), "+f"(c[3])
                        : "r"(af[mt][0]), "r"(af[mt][1]), "r"(af[mt][2]), "r"(af[mt][3]),
                          "r"(bf[nt][0]), "r"(bf[nt][1]));
                }
        }
        if (++sidx == NSTAGE) sidx = 0;
    }
    __syncthreads();

    // epilogue: stage accumulators to smem, coalesced float4 store + col max
    int ar = lane >> 2, ac = lane & 3;
#pragma unroll
    for (int mt = 0; mt < 2; mt++)
#pragma unroll
        for (int nt = 0; nt < 8; nt++) {
            int r = wm + mt * 16 + ar;
            int c = wn + nt * 8 + ac * 2;
            smem[r * LD2 + c]           = acc[mt][nt][0];
            smem[r * LD2 + c + 1]       = acc[mt][nt][1];
            smem[(r + 8) * LD2 + c]     = acc[mt][nt][2];
            smem[(r + 8) * LD2 + c + 1] = acc[mt][nt][3];
        }
    __syncthreads();

    float* Sb = g_S + (size_t)b * P * P;
    int c4 = (tid & 31) * 4;
    int rb = tid >> 5;
    float mx0 = -1e30f, mx1 = -1e30f, mx2 = -1e30f, mx3 = -1e30f;
#pragma unroll
    for (int i = 0; i < 16; i++) {
        int row = rb + i * 8;
        float4 v = *(float4*)&smem[row * LD2 + c4];
        *(float4*)&Sb[(size_t)(m0 + row) * P + n0 + c4] = v;
        mx0 = fmaxf(mx0, v.x); mx1 = fmaxf(mx1, v.y);
        mx2 = fmaxf(mx2, v.z); mx3 = fmaxf(mx3, v.w);
    }
    atomicMax(&cms[c4],     fenc(mx0));
    atomicMax(&cms[c4 + 1], fenc(mx1));
    atomicMax(&cms[c4 + 2], fenc(mx2));
    atomicMax(&cms[c4 + 3], fenc(mx3));
    __syncthreads();
    if (tid < 128) atomicMax(&g_colmax[(size_t)b * P + n0 + tid], cms[tid]);
}

// ---------------------------------------------------------------------------
__global__ void colsum_kernel(int P) {
    int b = blockIdx.z;
    int col = (blockIdx.x * 256 + threadIdx.x) * 4;
    int rps = P >> 6;   // gridDim.y == 64
    int r0 = blockIdx.y * rps;
    const unsigned* cm = g_colmax + (size_t)b * P + col;
    float s1[4], s2[4];
#pragma unroll
    for (int j = 0; j < 4; j++) {
        float M = fdec(cm[j]);
        s1[j] = 2.0f / (1.0f - M + 2e-5f);
        s2[j] = M * s1[j];
    }
    const float* Sb = g_S + (size_t)b * P * P;
    float a0 = 0.f, a1 = 0.f, a2 = 0.f, a3 = 0.f;
#pragma unroll 8
    for (int r = r0; r < r0 + rps; r++) {
        float4 v = *(const float4*)&Sb[(size_t)r * P + col];
        a0 += fast_exp(fmaf(v.x, s1[0], -s2[0]));
        a1 += fast_exp(fmaf(v.y, s1[1], -s2[1]));
        a2 += fast_exp(fmaf(v.z, s1[2], -s2[2]));
        a3 += fast_exp(fmaf(v.w, s1[3], -s2[3]));
    }
    float* Zb = g_Z + (size_t)b * P + col;
    atomicAdd(&Zb[0], a0);
    atomicAdd(&Zb[1], a1);
    atomicAdd(&Zb[2], a2);
    atomicAdd(&Zb[3], a3);
}

__global__ void aux_kernel(int total) {
    int i = blockIdx.x * blockDim.x + threadIdx.x;
    if (i >= total) return;
    float M = fdec(g_colmax[i]);
    float s1 = 2.0f / (1.0f - M + 2e-5f);
    g_s1[i] = s1;
    g_aux[i] = fmaf(M, s1, logf(g_Z[i]));
}

__global__ void rowmax_kernel(int P) {
    int b = blockIdx.y;
    int row = blockIdx.x * 8 + (threadIdx.x >> 5);
    int lane = threadIdx.x & 31;
    const float* Sr  = g_S + (size_t)b * P * P + (size_t)row * P;
    const float* s1b = g_s1 + (size_t)b * P;
    const float* axb = g_aux + (size_t)b * P;
    float mxa = -1e30f, mxb = -1e30f;
    for (int c = lane * 4; c < P; c += 256) {
        float4 v0 = *(const float4*)&Sr[c];
        float4 v1 = *(const float4*)&Sr[c + 128];
        float4 s0 = *(const float4*)&s1b[c];
        float4 s1v = *(const float4*)&s1b[c + 128];
        float4 a0 = *(const float4*)&axb[c];
        float4 a1 = *(const float4*)&axb[c + 128];
        mxa = fmaxf(mxa, fmaf(v0.x, s0.x, -a0.x));
        mxa = fmaxf(mxa, fmaf(v0.y, s0.y, -a0.y));
        mxa = fmaxf(mxa, fmaf(v0.z, s0.z, -a0.z));
        mxa = fmaxf(mxa, fmaf(v0.w, s0.w, -a0.w));
        mxb = fmaxf(mxb, fmaf(v1.x, s1v.x, -a1.x));
        mxb = fmaxf(mxb, fmaf(v1.y, s1v.y, -a1.y));
        mxb = fmaxf(mxb, fmaf(v1.z, s1v.z, -a1.z));
        mxb = fmaxf(mxb, fmaf(v1.w, s1v.w, -a1.w));
    }
    float mx = fmaxf(mxa, mxb);
#pragma unroll
    for (int o = 16; o; o >>= 1) mx = fmaxf(mx, __shfl_xor_sync(0xffffffffu, mx, o));
    if (lane == 0) g_rowmax[(size_t)b * P + row] = mx;
}

__global__ void loss_kernel(int P, float w, float* out) {
    int b = blockIdx.x;
    __shared__ float red[256];
    float s = 0.f;
    for (int p = threadIdx.x; p < P; p += 256)
        s += fast_exp(g_rowmax[(size_t)b * P + p]);
    red[threadIdx.x] = s;
    __syncthreads();
    for (int st = 128; st; st >>= 1) {
        if (threadIdx.x < (unsigned)st) red[threadIdx.x] += red[threadIdx.x + st];
        __syncthreads();
    }
    if (threadIdx.x == 0) atomicAdd(out, -w * logf(red[0] / (float)P));
}

// ---------------------------------------------------------------------------
#define GEMM_SMEM (128 * LD2 * 4)   // 67584 B (>= 6*ASTAGE = 52224)

static void run_layer(const float* gen, const float* tar, int B, int C, int P,
                      float w, float* out, int zero_out, int p4shift) {
    int total = B * P;
    init_kernel<<<(total + 255) / 256, 256>>>(total, zero_out, out);
    {
        int CPS = 8;                      // channels per split
        dim3 g(P / 1024, C / CPS, B);
        stats_kernel<<<g, 256>>>(gen, tar, C, P, CPS);
    }
    finalize_kernel<<<(total + 255) / 256, 256>>>(total, C);
    {
        dim3 g(C * P / 4 / 256, B);
        write_kernel<<<g, 256>>>(gen, tar, C, P, p4shift);
    }
    {
        dim3 g(P / 128, P / 128, B);
        gemm_fp16_colmax<<<g, 256, GEMM_SMEM>>>(C, P);
    }
    {
        dim3 g(P / 1024, 64, B);
        colsum_kernel<<<g, 256>>>(P);
    }
    aux_kernel<<<(total + 255) / 256, 256>>>(total);
    {
        dim3 g(P / 8, B);
        rowmax_kernel<<<g, 256>>>(P);
    }
    loss_kernel<<<B, 256>>>(P, w, out);
}

extern "C" void kernel_launch(void* const* d_in, const int* in_sizes, int n_in,
                              void* d_out, int out_size) {
    const float* g3 = (const float*)d_in[0];  // gen_relu3_2 [4,256,64,64]
    const float* t3 = (const float*)d_in[1];  // tar_relu3_2
    const float* g4 = (const float*)d_in[2];  // gen_relu4_2 [4,512,32,32]
    const float* t4 = (const float*)d_in[3];  // tar_relu4_2
    float* out = (float*)d_out;

    cudaFuncSetAttribute(gemm_fp16_colmax,
                         cudaFuncAttributeMaxDynamicSharedMemorySize, GEMM_SMEM);

    run_layer(g3, t3, 4, 256, 64 * 64, 1.0f, out, 1, 10);  // style w=1
    run_layer(g4, t4, 4, 512, 32 * 32, 2.0f, out, 0, 8);   // style + content w=2
}

// round 6
// speedup vs baseline: 4.0093x; 1.4423x over previous
#include <cuda_runtime.h>
#include <cuda_fp16.h>
#include <cstdint>
#include <math.h>

// ---------------------------------------------------------------------------
// IDMRF loss. S stored as fp16 (|S|<=1). See earlier rounds for derivation.
// ---------------------------------------------------------------------------

#define MAXB 4
#define MAXP 4096
#define MAX_PB (MAXB * MAXP)
#define MAXSPLIT 64

__device__ __half   g_S[(size_t)MAXB * MAXP * MAXP];   // 128 MiB scratch
__device__ __half   g_tn[(size_t)MAXB * 256 * 4096];
__device__ __half   g_gn[(size_t)MAXB * 256 * 4096];
__device__ unsigned g_colmax[MAX_PB];
__device__ float    g_Z[MAX_PB];
__device__ float    g_s1[MAX_PB];
__device__ float    g_aux[MAX_PB];
__device__ float    g_rowmax[MAX_PB];
// split-K normalize partials [split][b*P+hw]
__device__ float    g_pst[MAXSPLIT * MAX_PB], g_pstt[MAXSPLIT * MAX_PB];
__device__ float    g_psg[MAXSPLIT * MAX_PB], g_psgg[MAXSPLIT * MAX_PB];
__device__ float    g_mean[MAX_PB], g_nt[MAX_PB], g_ng[MAX_PB];

__device__ __forceinline__ unsigned fenc(float f) {
    unsigned u = __float_as_uint(f);
    return (u & 0x80000000u) ? ~u : (u | 0x80000000u);
}
__device__ __forceinline__ float fdec(unsigned u) {
    return __uint_as_float((u & 0x80000000u) ? (u ^ 0x80000000u) : ~u);
}

__device__ __forceinline__ float fast_exp(float x) {
    float y = fmaxf(x * 1.4426950408889634f, -126.0f);
    float n = rintf(y);
    float f = y - n;
    float p = 1.3333558e-3f;
    p = fmaf(p, f, 9.6181291e-3f);
    p = fmaf(p, f, 5.5504109e-2f);
    p = fmaf(p, f, 2.4022651e-1f);
    p = fmaf(p, f, 6.9314718e-1f);
    p = fmaf(p, f, 1.0f);
    return p * __uint_as_float(((unsigned)((int)n + 127)) << 23);
}

__device__ __forceinline__ void ldsm4t(uint32_t& r0, uint32_t& r1,
                                       uint32_t& r2, uint32_t& r3, unsigned addr) {
    asm volatile("ldmatrix.sync.aligned.m8n8.x4.trans.shared.b16 {%0,%1,%2,%3},[%4];"
                 : "=r"(r0), "=r"(r1), "=r"(r2), "=r"(r3) : "r"(addr));
}

// ---- normalize phase 1: split-K partial stats, no atomics ------------------
__global__ void stats_kernel(const float* __restrict__ gen,
                             const float* __restrict__ tar,
                             int C, int P, int CPS) {
    int hw = blockIdx.x * 1024 + threadIdx.x * 4;
    int b = blockIdx.z;
    int sp = blockIdx.y;
    int c0 = sp * CPS;
    const float* g = gen + (size_t)b * C * P + (size_t)c0 * P + hw;
    const float* t = tar + (size_t)b * C * P + (size_t)c0 * P + hw;
    float st[4] = {0,0,0,0}, stt[4] = {0,0,0,0}, sg[4] = {0,0,0,0}, sgg[4] = {0,0,0,0};
#pragma unroll 4
    for (int c = 0; c < CPS; c++) {
        float4 tv = *(const float4*)&t[(size_t)c * P];
        float4 gv = *(const float4*)&g[(size_t)c * P];
        st[0] += tv.x; stt[0] += tv.x * tv.x; sg[0] += gv.x; sgg[0] += gv.x * gv.x;
        st[1] += tv.y; stt[1] += tv.y * tv.y; sg[1] += gv.y; sgg[1] += gv.y * gv.y;
        st[2] += tv.z; stt[2] += tv.z * tv.z; sg[2] += gv.z; sgg[2] += gv.z * gv.z;
        st[3] += tv.w; stt[3] += tv.w * tv.w; sg[3] += gv.w; sgg[3] += gv.w * gv.w;
    }
    size_t base = (size_t)sp * MAX_PB + (size_t)b * P + hw;
    *(float4*)&g_pst[base]  = make_float4(st[0], st[1], st[2], st[3]);
    *(float4*)&g_pstt[base] = make_float4(stt[0], stt[1], stt[2], stt[3]);
    *(float4*)&g_psg[base]  = make_float4(sg[0], sg[1], sg[2], sg[3]);
    *(float4*)&g_psgg[base] = make_float4(sgg[0], sgg[1], sgg[2], sgg[3]);
}

// ---- phase 2: reduce partials, compute mean/norms; zero colmax/Z/out -------
__global__ void finalize_kernel(int total, int C, int NS, int zero_out, float* out) {
    int i = blockIdx.x * blockDim.x + threadIdx.x;
    if (i >= total) return;
    float st = 0.f, stt = 0.f, sg = 0.f, sgg = 0.f;
    for (int s = 0; s < NS; s++) {
        size_t o = (size_t)s * MAX_PB + i;
        st += g_pst[o]; stt += g_pstt[o]; sg += g_psg[o]; sgg += g_psgg[o];
    }
    float mean = st / (float)C;
    float vt = stt - (float)C * mean * mean;
    float vg = sgg - 2.f * mean * sg + (float)C * mean * mean;
    g_mean[i] = mean;
    g_nt[i] = rsqrtf(fmaxf(vt, 1e-30f));
    g_ng[i] = rsqrtf(fmaxf(vg, 1e-30f));
    g_colmax[i] = 0u;
    g_Z[i] = 0.f;
    if (i == 0 && zero_out) out[0] = 0.f;
}

// ---- phase 3: write normalized fp16 features, fully parallel ----------------
__global__ void write_kernel(const float* __restrict__ gen,
                             const float* __restrict__ tar,
                             int C, int P, int p4shift) {
    int idx = blockIdx.x * 256 + threadIdx.x;
    int b = blockIdx.y;
    int c = idx >> p4shift;
    int hw = (idx & ((1 << p4shift) - 1)) * 4;
    size_t off = (size_t)b * C * P + (size_t)c * P + hw;
    size_t pb = (size_t)b * P + hw;
    float4 tv = *(const float4*)&tar[off];
    float4 gv = *(const float4*)&gen[off];
    float4 mean = *(const float4*)&g_mean[pb];
    float4 nt   = *(const float4*)&g_nt[pb];
    float4 ng   = *(const float4*)&g_ng[pb];
    __half2 t01 = __floats2half2_rn((tv.x - mean.x) * nt.x, (tv.y - mean.y) * nt.y);
    __half2 t23 = __floats2half2_rn((tv.z - mean.z) * nt.z, (tv.w - mean.w) * nt.w);
    __half2 g01 = __floats2half2_rn((gv.x - mean.x) * ng.x, (gv.y - mean.y) * ng.y);
    __half2 g23 = __floats2half2_rn((gv.z - mean.z) * ng.z, (gv.w - mean.w) * ng.w);
    uint2 tp, gp;
    tp.x = *(unsigned*)&t01; tp.y = *(unsigned*)&t23;
    gp.x = *(unsigned*)&g01; gp.y = *(unsigned*)&g23;
    *(uint2*)&g_tn[off] = tp;
    *(uint2*)&g_gn[off] = gp;
}

// ---------------------------------------------------------------------------
// FP16 tensor-core GEMM: S = tn^T @ gn, mma m16n8k16, 128x128 block, BK=32,
// 3-stage cp.async pipeline, ldmatrix.x4.trans; fp16 S store + fused colmax.
// ---------------------------------------------------------------------------
#define LDH 136                      // smem row stride in halves (272 B)
#define ASTAGE (32 * LDH * 2)        // 8704 B per tile per stage
#define NSTAGE 3
#define SLD 136                      // epilogue staging stride (halves)

__global__ void __launch_bounds__(256)
gemm_fp16_colmax(int C, int P) {
    extern __shared__ float smem[];
    __shared__ unsigned cms[128];
    int b  = blockIdx.z;
    int m0 = blockIdx.y * 128;
    int n0 = blockIdx.x * 128;
    const __half* Ab = g_tn + (size_t)b * C * P;
    const __half* Bb = g_gn + (size_t)b * C * P;
    int tid = threadIdx.x, lane = tid & 31, wid = tid >> 5;
    int wm = (wid & 3) * 32;   // 4 warps in M
    int wn = (wid >> 2) * 64;  // 2 warps in N
    if (tid < 128) cms[tid] = 0u;

    unsigned sA = (unsigned)__cvta_generic_to_shared(smem);
    unsigned sB = sA + (unsigned)NSTAGE * ASTAGE;

    float acc[2][8][4];
#pragma unroll
    for (int mt = 0; mt < 2; mt++)
#pragma unroll
        for (int nt = 0; nt < 8; nt++)
#pragma unroll
            for (int j = 0; j < 4; j++) acc[mt][nt][j] = 0.f;

    int nk = C / 32;

    auto issue_stage = [&](int s, int k0) {
#pragma unroll
        for (int i = 0; i < 2; i++) {
            int idx = tid + i * 256;
            int r = idx >> 4;
            int cm = (idx & 15) * 8;
            unsigned da = sA + (unsigned)s * ASTAGE + (unsigned)((r * LDH + cm) * 2);
            const __half* pa = Ab + (size_t)(k0 + r) * P + m0 + cm;
            asm volatile("cp.async.cg.shared.global [%0], [%1], 16;" :: "r"(da), "l"(pa));
            unsigned db = sB + (unsigned)s * ASTAGE + (unsigned)((r * LDH + cm) * 2);
            const __half* pb = Bb + (size_t)(k0 + r) * P + n0 + cm;
            asm volatile("cp.async.cg.shared.global [%0], [%1], 16;" :: "r"(db), "l"(pb));
        }
    };

    issue_stage(0, 0);
    asm volatile("cp.async.commit_group;");
    issue_stage(1, 32);
    asm volatile("cp.async.commit_group;");

    int g = lane >> 3, li = lane & 7;
    int akoff = (g >> 1) << 3, amoff = (g & 1) << 3;
    int bkoff = (g & 1) << 3,  bnoff = (g >> 1) << 3;

    int sidx = 0;
    for (int kt = 0; kt < nk; kt++) {
        asm volatile("cp.async.wait_group 1;");
        __syncthreads();
        if (kt + 2 < nk) {
            int s2 = sidx + 2; if (s2 >= NSTAGE) s2 -= NSTAGE;
            issue_stage(s2, (kt + 2) * 32);
        }
        asm volatile("cp.async.commit_group;");
        unsigned aS = sA + (unsigned)sidx * ASTAGE;
        unsigned bS = sB + (unsigned)sidx * ASTAGE;
#pragma unroll
        for (int k16 = 0; k16 < 2; k16++) {
            int kb = k16 * 16;
            uint32_t af[2][4];
#pragma unroll
            for (int mt = 0; mt < 2; mt++) {
                int row = kb + akoff + li;
                int col = wm + mt * 16 + amoff;
                ldsm4t(af[mt][0], af[mt][1], af[mt][2], af[mt][3],
                       aS + (unsigned)((row * LDH + col) * 2));
            }
            uint32_t bf[8][2];
#pragma unroll
            for (int np = 0; np < 4; np++) {
                int row = kb + bkoff + li;
                int col = wn + np * 16 + bnoff;
                uint32_t r0, r1, r2, r3;
                ldsm4t(r0, r1, r2, r3, bS + (unsigned)((row * LDH + col) * 2));
                bf[np * 2][0] = r0; bf[np * 2][1] = r1;
                bf[np * 2 + 1][0] = r2; bf[np * 2 + 1][1] = r3;
            }
#pragma unroll
            for (int mt = 0; mt < 2; mt++)
#pragma unroll
                for (int nt = 0; nt < 8; nt++) {
                    float* c = acc[mt][nt];
                    asm volatile(
                        "mma.sync.aligned.m16n8k16.row.col.f32.f16.f16.f32 "
                        "{%0,%1,%2,%3},{%4,%5,%6,%7},{%8,%9},{%0,%1,%2,%3};"
                        : "+f"(c[0]), "+f"(c[1]), "+f"(c[2]), "+f"(c[3])
                        : "r"(af[mt][0]), "r"(af[mt][1]), "r"(af[mt][2]), "r"(af[mt][3]),
                          "r"(bf[nt][0]), "r"(bf[nt][1]));
                }
        }
        if (++sidx == NSTAGE) sidx = 0;
    }
    __syncthreads();

    // epilogue: colmax from fp32 acc; stage fp16 to smem; coalesced 16B stores
    int ar = lane >> 2, ac = lane & 3;
    __half* hs = (__half*)smem;
#pragma unroll
    for (int mt = 0; mt < 2; mt++)
#pragma unroll
        for (int nt = 0; nt < 8; nt++) {
            int r = wm + mt * 16 + ar;
            int c = wn + nt * 8 + ac * 2;
            float* a = acc[mt][nt];
            *(__half2*)&hs[r * SLD + c]       = __floats2half2_rn(a[0], a[1]);
            *(__half2*)&hs[(r + 8) * SLD + c] = __floats2half2_rn(a[2], a[3]);
            // column maxima from fp32 accumulators
            float mx01 = fmaxf(a[0], a[2]);
            float mx11 = fmaxf(a[1], a[3]);
            atomicMax(&cms[c],     fenc(mx01));
            atomicMax(&cms[c + 1], fenc(mx11));
        }
    __syncthreads();

    __half* Sb = g_S + (size_t)b * P * P;
    int ch = tid & 15;            // 16B chunk within 128-col row
    int r0 = tid >> 4;            // 16 rows per iteration
#pragma unroll
    for (int i = 0; i < 8; i++) {
        int row = r0 + i * 16;
        uint4 v = *(uint4*)&hs[row * SLD + ch * 8];
        *(uint4*)&Sb[(size_t)(m0 + row) * P + n0 + ch * 8] = v;
    }
    if (tid < 128) atomicMax(&g_colmax[(size_t)b * P + n0 + tid], cms[tid]);
}

// ---------------------------------------------------------------------------
// Z[col] += sum over row split of exp(S*s1 - s2); 4 fp16 cols per thread
__global__ void colsum_kernel(int P) {
    int b = blockIdx.z;
    int col = (blockIdx.x * 256 + threadIdx.x) * 4;
    int rps = P >> 6;   // gridDim.y == 64
    int r0 = blockIdx.y * rps;
    const unsigned* cm = g_colmax + (size_t)b * P + col;
    float s1[4], s2[4];
#pragma unroll
    for (int j = 0; j < 4; j++) {
        float M = fdec(cm[j]);
        s1[j] = 2.0f / (1.0f - M + 2e-5f);
        s2[j] = M * s1[j];
    }
    const __half* Sb = g_S + (size_t)b * P * P;
    float a0 = 0.f, a1 = 0.f, a2 = 0.f, a3 = 0.f;
#pragma unroll 8
    for (int r = r0; r < r0 + rps; r++) {
        uint2 u = *(const uint2*)&Sb[(size_t)r * P + col];
        float2 v01 = __half22float2(*(__half2*)&u.x);
        float2 v23 = __half22float2(*(__half2*)&u.y);
        a0 += fast_exp(fmaf(v01.x, s1[0], -s2[0]));
        a1 += fast_exp(fmaf(v01.y, s1[1], -s2[1]));
        a2 += fast_exp(fmaf(v23.x, s1[2], -s2[2]));
        a3 += fast_exp(fmaf(v23.y, s1[3], -s2[3]));
    }
    float* Zb = g_Z + (size_t)b * P + col;
    atomicAdd(&Zb[0], a0);
    atomicAdd(&Zb[1], a1);
    atomicAdd(&Zb[2], a2);
    atomicAdd(&Zb[3], a3);
}

__global__ void aux_kernel(int total) {
    int i = blockIdx.x * blockDim.x + threadIdx.x;
    if (i >= total) return;
    float M = fdec(g_colmax[i]);
    float s1 = 2.0f / (1.0f - M + 2e-5f);
    g_s1[i] = s1;
    g_aux[i] = fmaf(M, s1, logf(g_Z[i]));
}

// per-row max of (S*s1 - aux); one warp per row, 8 fp16 per lane per step
__global__ void rowmax_kernel(int P) {
    int b = blockIdx.y;
    int row = blockIdx.x * 8 + (threadIdx.x >> 5);
    int lane = threadIdx.x & 31;
    const __half* Sr = g_S + (size_t)b * P * P + (size_t)row * P;
    const float* s1b = g_s1 + (size_t)b * P;
    const float* axb = g_aux + (size_t)b * P;
    float mx = -1e30f;
    for (int c = lane * 8; c < P; c += 256) {
        uint4 u = *(const uint4*)&Sr[c];
        float4 s0 = *(const float4*)&s1b[c];
        float4 s1v = *(const float4*)&s1b[c + 4];
        float4 a0 = *(const float4*)&axb[c];
        float4 a1 = *(const float4*)&axb[c + 4];
        float2 v0 = __half22float2(*(__half2*)&u.x);
        float2 v1 = __half22float2(*(__half2*)&u.y);
        float2 v2 = __half22float2(*(__half2*)&u.z);
        float2 v3 = __half22float2(*(__half2*)&u.w);
        mx = fmaxf(mx, fmaf(v0.x, s0.x, -a0.x));
        mx = fmaxf(mx, fmaf(v0.y, s0.y, -a0.y));
        mx = fmaxf(mx, fmaf(v1.x, s0.z, -a0.z));
        mx = fmaxf(mx, fmaf(v1.y, s0.w, -a0.w));
        mx = fmaxf(mx, fmaf(v2.x, s1v.x, -a1.x));
        mx = fmaxf(mx, fmaf(v2.y, s1v.y, -a1.y));
        mx = fmaxf(mx, fmaf(v3.x, s1v.z, -a1.z));
        mx = fmaxf(mx, fmaf(v3.y, s1v.w, -a1.w));
    }
#pragma unroll
    for (int o = 16; o; o >>= 1) mx = fmaxf(mx, __shfl_xor_sync(0xffffffffu, mx, o));
    if (lane == 0) g_rowmax[(size_t)b * P + row] = mx;
}

__global__ void loss_kernel(int P, float w, float* out) {
    int b = blockIdx.x;
    __shared__ float red[256];
    float s = 0.f;
    for (int p = threadIdx.x; p < P; p += 256)
        s += fast_exp(g_rowmax[(size_t)b * P + p]);
    red[threadIdx.x] = s;
    __syncthreads();
    for (int st = 128; st; st >>= 1) {
        if (threadIdx.x < (unsigned)st) red[threadIdx.x] += red[threadIdx.x + st];
        __syncthreads();
    }
    if (threadIdx.x == 0) atomicAdd(out, -w * logf(red[0] / (float)P));
}

// ---------------------------------------------------------------------------
#define GEMM_SMEM 67584   // >= 6*ASTAGE (52224) and >= 128*SLD*2 (34816)

static void run_layer(const float* gen, const float* tar, int B, int C, int P,
                      float w, float* out, int zero_out, int p4shift) {
    int total = B * P;
    int CPS = 8, NS = C / CPS;
    {
        dim3 g(P / 1024, NS, B);
        stats_kernel<<<g, 256>>>(gen, tar, C, P, CPS);
    }
    finalize_kernel<<<(total + 255) / 256, 256>>>(total, C, NS, zero_out, out);
    {
        dim3 g(C * P / 4 / 256, B);
        write_kernel<<<g, 256>>>(gen, tar, C, P, p4shift);
    }
    {
        dim3 g(P / 128, P / 128, B);
        gemm_fp16_colmax<<<g, 256, GEMM_SMEM>>>(C, P);
    }
    {
        dim3 g(P / 1024, 64, B);
        colsum_kernel<<<g, 256>>>(P);
    }
    aux_kernel<<<(total + 255) / 256, 256>>>(total);
    {
        dim3 g(P / 8, B);
        rowmax_kernel<<<g, 256>>>(P);
    }
    loss_kernel<<<B, 256>>>(P, w, out);
}

extern "C" void kernel_launch(void* const* d_in, const int* in_sizes, int n_in,
                              void* d_out, int out_size) {
    const float* g3 = (const float*)d_in[0];  // gen_relu3_2 [4,256,64,64]
    const float* t3 = (const float*)d_in[1];  // tar_relu3_2
    const float* g4 = (const float*)d_in[2];  // gen_relu4_2 [4,512,32,32]
    const float* t4 = (const float*)d_in[3];  // tar_relu4_2
    float* out = (float*)d_out;

    cudaFuncSetAttribute(gemm_fp16_colmax,
                         cudaFuncAttributeMaxDynamicSharedMemorySize, GEMM_SMEM);

    run_layer(g3, t3, 4, 256, 64 * 64, 1.0f, out, 1, 10);  // style w=1
    run_layer(g4, t4, 4, 512, 32 * 32, 2.0f, out, 0, 8);   // style + content w=2
}